// round 5
// baseline (speedup 1.0000x reference)
#include <cuda_runtime.h>
#include <math.h>
#include <stdint.h>

#define BATCH 4
#define SEQ   4096
#define DIM   1024
#define NH    4
#define DH    256
#define FFD   4096
#define TOK   (BATCH*SEQ)   /* 16384 */
#define NBH   (BATCH*NH)    /* 16 */
#define KCH   16
#define CHUNK (SEQ/KCH)     /* 256 */

/* mma GEMM tiling: 128x128 CTA tile, 512 threads, 16 warps of 32x32 */
#define TM 128
#define TN 128
#define TK 32
#define APITCH 36
#define BPITCH 136
#define ABYTES (TM*APITCH*4)      /* 18432 */
#define BBYTES (TK*BPITCH*4)      /* 17408 */
#define SMEM2  (2*(ABYTES+BBYTES)) /* 71680 */

// ---------------- scratch ---------------------------------------------------
__device__ float g_h   [(size_t)TOK*DIM];
__device__ float g_q   [(size_t)NBH*SEQ*DH];
__device__ float g_k   [(size_t)NBH*SEQ*DH];
__device__ float g_v   [(size_t)NBH*SEQ*DH];
__device__ float g_ctx [(size_t)NBH*DH*DH];
__device__ float g_attn[(size_t)TOK*DIM];
__device__ float g_x1  [(size_t)TOK*DIM];
__device__ float g_x2  [(size_t)TOK*DIM];
__device__ float g_ff  [(size_t)TOK*FFD];
__device__ float g_part[NBH*KCH*2*DH];

__device__ __forceinline__ float gelu_tanh(float x) {
    float x3 = x*x*x;
    return 0.5f*x*(1.0f + tanhf(0.7978845608028654f*(x + 0.044715f*x3)));
}

__device__ __forceinline__ uint32_t smem_u32(const void* p) {
    uint32_t a;
    asm("{ .reg .u64 t; cvta.to.shared.u64 t, %1; cvt.u32.u64 %0, t; }" : "=r"(a) : "l"(p));
    return a;
}
__device__ __forceinline__ void cp16(uint32_t dst, const void* src) {
    asm volatile("cp.async.cg.shared.global [%0], [%1], 16;" :: "r"(dst), "l"(src));
}
__device__ __forceinline__ uint32_t f2tf32(float x) {
    uint32_t u;
    asm("cvt.rna.tf32.f32 %0, %1;" : "=r"(u) : "f"(x));
    return u;
}
__device__ __forceinline__ void mma_tf32(float* c, uint32_t a0, uint32_t a1, uint32_t a2,
                                         uint32_t a3, uint32_t b0, uint32_t b1) {
    asm volatile("mma.sync.aligned.m16n8k8.row.col.f32.tf32.tf32.f32 "
        "{%0,%1,%2,%3}, {%4,%5,%6,%7}, {%8,%9}, {%0,%1,%2,%3};"
        : "+f"(c[0]), "+f"(c[1]), "+f"(c[2]), "+f"(c[3])
        : "r"(a0), "r"(a1), "r"(a2), "r"(a3), "r"(b0), "r"(b1));
}

// ---------------- mma.sync tf32 GEMM, 128x128 tiles, 512 threads ------------
// MODE 0: C = acc + bias
// MODE 1: C = acc + bias + res
// MODE 2: C = gelu(acc + bias)
// MODE 3: C = acc scattered to [b,h,n,dh] (A indexed over TOK rows)
// MODE 4: batched attn out: A = q + z*SEQ*DH, W = ctx + z*DH*DH, scatter to [b,n,d]
template<int MODE>
__global__ void __launch_bounds__(512, 1)
gemm_mma(const float* __restrict__ A, const float* __restrict__ W,
         const float* __restrict__ bias, const float* __restrict__ res,
         float* __restrict__ C, int Ncols, int K)
{
    extern __shared__ char dsm[];
    float* As[2] = { (float*)dsm,                (float*)(dsm + ABYTES) };
    float* Bs[2] = { (float*)(dsm + 2*ABYTES),   (float*)(dsm + 2*ABYTES + BBYTES) };
    const uint32_t aAs[2] = { smem_u32(As[0]), smem_u32(As[1]) };
    const uint32_t aBs[2] = { smem_u32(Bs[0]), smem_u32(Bs[1]) };

    if (MODE == 4) {
        A += (size_t)blockIdx.z * SEQ * DH;
        W += (size_t)blockIdx.z * DH * DH;
    }

    const int tid  = threadIdx.x;
    const int lane = tid & 31;
    const int w    = tid >> 5;          /* 0..15 */
    const int m0w  = (w >> 2) * 32;     /* warp M offset in tile */
    const int n0w  = (w & 3) * 32;      /* warp N offset in tile */
    const int row0 = blockIdx.y * TM;
    const int col0 = blockIdx.x * TN;
    const int NT   = K / TK;

    const int lr = lane >> 2;           /* 0..7  */
    const int lc = lane & 3;            /* 0..3  */

    auto fill = [&](int buf, int k0) {
        /* A: 128 rows x 32 cols -> 1024 float4, 2 per thread */
        #pragma unroll
        for (int j = 0; j < 2; j++) {
            int f  = tid + 512*j;
            int r  = f >> 3, c4 = f & 7;
            cp16(aAs[buf] + (uint32_t)(r*APITCH + c4*4)*4,
                 A + (size_t)(row0 + r)*K + k0 + c4*4);
        }
        /* B: 32 rows x 128 cols -> 1024 float4, 2 per thread */
        #pragma unroll
        for (int j = 0; j < 2; j++) {
            int f  = tid + 512*j;
            int kr = f >> 5, c4 = f & 31;
            cp16(aBs[buf] + (uint32_t)(kr*BPITCH + c4*4)*4,
                 W + (size_t)(k0 + kr)*Ncols + col0 + c4*4);
        }
        asm volatile("cp.async.commit_group;");
    };

    float acc[2][4][4];
    #pragma unroll
    for (int i = 0; i < 2; i++)
        #pragma unroll
        for (int j = 0; j < 4; j++)
            #pragma unroll
            for (int r = 0; r < 4; r++) acc[i][j][r] = 0.f;

    fill(0, 0);

    for (int t = 0; t < NT; t++) {
        if (t + 1 < NT) {
            fill((t + 1) & 1, (t + 1) * TK);
            asm volatile("cp.async.wait_group 1;");
        } else {
            asm volatile("cp.async.wait_group 0;");
        }
        __syncthreads();

        const float* Ab = As[t & 1];
        const float* Bb = Bs[t & 1];

        #pragma unroll
        for (int kk = 0; kk < 4; kk++) {
            const int kc = kk*8 + lc;
            uint32_t af[2][4];
            #pragma unroll
            for (int mf = 0; mf < 2; mf++) {
                const float* ap = Ab + (m0w + mf*16 + lr)*APITCH + kc;
                af[mf][0] = f2tf32(ap[0]);
                af[mf][1] = f2tf32(ap[8*APITCH]);
                af[mf][2] = f2tf32(ap[4]);
                af[mf][3] = f2tf32(ap[8*APITCH + 4]);
            }
            uint32_t bf[4][2];
            #pragma unroll
            for (int nf = 0; nf < 4; nf++) {
                const float* bp = Bb + kc*BPITCH + n0w + nf*8 + lr;
                bf[nf][0] = f2tf32(bp[0]);
                bf[nf][1] = f2tf32(bp[4*BPITCH]);
            }
            #pragma unroll
            for (int mf = 0; mf < 2; mf++)
                #pragma unroll
                for (int nf = 0; nf < 4; nf++)
                    mma_tf32(acc[mf][nf], af[mf][0], af[mf][1], af[mf][2], af[mf][3],
                             bf[nf][0], bf[nf][1]);
        }
        __syncthreads();
    }

    // ---- epilogue ----
    #pragma unroll
    for (int mf = 0; mf < 2; mf++) {
        #pragma unroll
        for (int half = 0; half < 2; half++) {
            const int grow = row0 + m0w + mf*16 + lr + half*8;
            #pragma unroll
            for (int nf = 0; nf < 4; nf++) {
                const int gcol = col0 + n0w + nf*8 + 2*lc;
                float v0 = acc[mf][nf][half*2 + 0];
                float v1 = acc[mf][nf][half*2 + 1];
                if (MODE == 3) {
                    const int head = gcol >> 8;
                    const int dh0  = gcol & 255;
                    const int b_   = grow >> 12;
                    const int n_   = grow & 4095;
                    float* op = C + ((size_t)((b_*NH + head)*SEQ + n_))*DH + dh0;
                    *(float2*)op = make_float2(v0, v1);
                } else if (MODE == 4) {
                    const int b_   = blockIdx.z >> 2;
                    const int head = blockIdx.z & 3;
                    float* op = C + ((size_t)(b_*SEQ + grow))*DIM + head*DH + gcol;
                    *(float2*)op = make_float2(v0, v1);
                } else {
                    v0 += bias[gcol];
                    v1 += bias[gcol + 1];
                    if (MODE == 2) { v0 = gelu_tanh(v0); v1 = gelu_tanh(v1); }
                    if (MODE == 1) {
                        const float2 rv = *(const float2*)(res + (size_t)grow*Ncols + gcol);
                        v0 += rv.x; v1 += rv.y;
                    }
                    *(float2*)(C + (size_t)grow*Ncols + gcol) = make_float2(v0, v1);
                }
            }
        }
    }
}

// ---------------- LayerNorm -------------------------------------------------
__global__ void ln_kernel(const float* __restrict__ x, const float* __restrict__ g,
                          const float* __restrict__ b, float* __restrict__ out)
{
    __shared__ float red[16];
    __shared__ float s_mu, s_rstd;
    const int row = blockIdx.x, t = threadIdx.x;
    const float4 v = ((const float4*)(x + (size_t)row*DIM))[t];
    float s  = v.x + v.y + v.z + v.w;
    float ss = fmaf(v.x,v.x, fmaf(v.y,v.y, fmaf(v.z,v.z, v.w*v.w)));
    #pragma unroll
    for (int o = 16; o > 0; o >>= 1) {
        s  += __shfl_xor_sync(0xffffffffu, s,  o);
        ss += __shfl_xor_sync(0xffffffffu, ss, o);
    }
    const int w = t >> 5, lane = t & 31;
    if (lane == 0) { red[w] = s; red[8+w] = ss; }
    __syncthreads();
    if (t == 0) {
        float S = 0.f, SS = 0.f;
        #pragma unroll
        for (int i = 0; i < 8; i++) { S += red[i]; SS += red[8+i]; }
        float mu  = S  * (1.0f/DIM);
        float var = SS * (1.0f/DIM) - mu*mu;
        s_mu = mu; s_rstd = rsqrtf(var + 1e-5f);
    }
    __syncthreads();
    const float mu = s_mu, r = s_rstd;
    const float4 gv = ((const float4*)g)[t];
    const float4 bv = ((const float4*)b)[t];
    float4 o;
    o.x = (v.x-mu)*r*gv.x + bv.x;
    o.y = (v.y-mu)*r*gv.y + bv.y;
    o.z = (v.z-mu)*r*gv.z + bv.z;
    o.w = (v.w-mu)*r*gv.w + bv.w;
    ((float4*)(out + (size_t)row*DIM))[t] = o;
}

// ---------------- q softmax over head dim -----------------------------------
__global__ void qsm_kernel(float* __restrict__ q)
{
    const int warp = (blockIdx.x * blockDim.x + threadIdx.x) >> 5;
    const int lane = threadIdx.x & 31;
    float* row = q + (size_t)warp * DH;
    float v[8];
    float m = -INFINITY;
    #pragma unroll
    for (int j = 0; j < 8; j++) { v[j] = row[j*32 + lane] * 0.25f; m = fmaxf(m, v[j]); }
    #pragma unroll
    for (int o = 16; o > 0; o >>= 1) m = fmaxf(m, __shfl_xor_sync(0xffffffffu, m, o));
    float s = 0.f;
    #pragma unroll
    for (int j = 0; j < 8; j++) { v[j] = expf(v[j] - m); s += v[j]; }
    #pragma unroll
    for (int o = 16; o > 0; o >>= 1) s += __shfl_xor_sync(0xffffffffu, s, o);
    const float inv = 1.0f / s;
    #pragma unroll
    for (int j = 0; j < 8; j++) row[j*32 + lane] = v[j] * inv;
}

// ---------------- k softmax over sequence dim (2-pass chunked) --------------
__global__ void ksm_partial(const float* __restrict__ k, float* __restrict__ part)
{
    const int bh = blockIdx.y, ch = blockIdx.x, t = threadIdx.x;
    const float* kp = k + ((size_t)bh*SEQ + (size_t)ch*CHUNK)*DH + t;
    float m = -INFINITY, s = 0.f;
    for (int i = 0; i < CHUNK; i++) {
        const float vv = kp[(size_t)i*DH] * 0.25f;
        const float nm = fmaxf(m, vv);
        s = s*expf(m - nm) + expf(vv - nm);
        m = nm;
    }
    float* pp = part + (size_t)((bh*KCH + ch)*2)*DH;
    pp[t] = m; pp[DH + t] = s;
}

__global__ void ksm_norm(float* __restrict__ k, const float* __restrict__ part)
{
    const int bh = blockIdx.y, ch = blockIdx.x, t = threadIdx.x;
    float M = -INFINITY;
    #pragma unroll
    for (int c = 0; c < KCH; c++)
        M = fmaxf(M, part[(size_t)((bh*KCH + c)*2)*DH + t]);
    float S = 0.f;
    #pragma unroll
    for (int c = 0; c < KCH; c++) {
        const float* pp = part + (size_t)((bh*KCH + c)*2)*DH;
        S += pp[DH + t] * expf(pp[t] - M);
    }
    const float inv = 1.0f / S;
    float* kp = k + ((size_t)bh*SEQ + (size_t)ch*CHUNK)*DH + t;
    for (int i = 0; i < CHUNK; i++) {
        const float vv = kp[(size_t)i*DH] * 0.25f;
        kp[(size_t)i*DH] = expf(vv - M) * inv;
    }
}

// ---------------- ctx = k^T @ v  (per bh: 256x4096^T x 4096x256) ------------
__global__ void __launch_bounds__(256)
ctx_gemm(const float* __restrict__ k, const float* __restrict__ v, float* __restrict__ ctx)
{
    __shared__ float As[16][64];
    __shared__ float Bs[16][64];
    const int bh = blockIdx.z;
    const int m0 = blockIdx.y * 64, e0 = blockIdx.x * 64;
    const int tid = threadIdx.x;
    const int tx = tid & 15, ty = tid >> 4;
    const int lr = tid >> 4;
    const int lc = (tid & 15) * 4;
    const float* kb = k + (size_t)bh*SEQ*DH;
    const float* vb = v + (size_t)bh*SEQ*DH;
    float acc[4][4] = {};

    for (int n0 = 0; n0 < SEQ; n0 += 16) {
        *(float4*)&As[lr][lc] = *(const float4*)(kb + (size_t)(n0+lr)*DH + m0 + lc);
        *(float4*)&Bs[lr][lc] = *(const float4*)(vb + (size_t)(n0+lr)*DH + e0 + lc);
        __syncthreads();
        #pragma unroll
        for (int kk = 0; kk < 16; kk++) {
            float4 a = *(const float4*)&As[kk][ty*4];
            float4 b = *(const float4*)&Bs[kk][tx*4];
            const float ar[4] = {a.x,a.y,a.z,a.w};
            const float br[4] = {b.x,b.y,b.z,b.w};
            #pragma unroll
            for (int i = 0; i < 4; i++)
                #pragma unroll
                for (int j = 0; j < 4; j++)
                    acc[i][j] = fmaf(ar[i], br[j], acc[i][j]);
        }
        __syncthreads();
    }
    float* cb = ctx + (size_t)bh*DH*DH;
    #pragma unroll
    for (int i = 0; i < 4; i++)
        *(float4*)(cb + (size_t)(m0 + ty*4 + i)*DH + e0 + tx*4) =
            make_float4(acc[i][0], acc[i][1], acc[i][2], acc[i][3]);
}

// ---------------- launch ----------------------------------------------------
extern "C" void kernel_launch(void* const* d_in, const int* in_sizes, int n_in,
                              void* d_out, int out_size)
{
    const float* x    = (const float*)d_in[0];
    const float* ln1g = (const float*)d_in[1];
    const float* ln1b = (const float*)d_in[2];
    const float* wq   = (const float*)d_in[3];
    const float* wk   = (const float*)d_in[4];
    const float* wv   = (const float*)d_in[5];
    const float* wo   = (const float*)d_in[6];
    const float* bo   = (const float*)d_in[7];
    const float* ln2g = (const float*)d_in[8];
    const float* ln2b = (const float*)d_in[9];
    const float* wff1 = (const float*)d_in[10];
    const float* bff1 = (const float*)d_in[11];
    const float* wff2 = (const float*)d_in[12];
    const float* bff2 = (const float*)d_in[13];
    const float* wd   = (const float*)d_in[14];
    const float* bd   = (const float*)d_in[15];
    float* out = (float*)d_out;

    float *h,*q,*k,*v,*ctx,*attn,*x1,*x2,*ff,*part;
    cudaGetSymbolAddress((void**)&h,    g_h);
    cudaGetSymbolAddress((void**)&q,    g_q);
    cudaGetSymbolAddress((void**)&k,    g_k);
    cudaGetSymbolAddress((void**)&v,    g_v);
    cudaGetSymbolAddress((void**)&ctx,  g_ctx);
    cudaGetSymbolAddress((void**)&attn, g_attn);
    cudaGetSymbolAddress((void**)&x1,   g_x1);
    cudaGetSymbolAddress((void**)&x2,   g_x2);
    cudaGetSymbolAddress((void**)&ff,   g_ff);
    cudaGetSymbolAddress((void**)&part, g_part);

    cudaFuncSetAttribute(gemm_mma<0>, cudaFuncAttributeMaxDynamicSharedMemorySize, SMEM2);
    cudaFuncSetAttribute(gemm_mma<1>, cudaFuncAttributeMaxDynamicSharedMemorySize, SMEM2);
    cudaFuncSetAttribute(gemm_mma<2>, cudaFuncAttributeMaxDynamicSharedMemorySize, SMEM2);
    cudaFuncSetAttribute(gemm_mma<3>, cudaFuncAttributeMaxDynamicSharedMemorySize, SMEM2);
    cudaFuncSetAttribute(gemm_mma<4>, cudaFuncAttributeMaxDynamicSharedMemorySize, SMEM2);

    // --- attention block ---
    ln_kernel<<<TOK, 256>>>(x, ln1g, ln1b, h);
    gemm_mma<3><<<dim3(8, 128), 512, SMEM2>>>(h, wq, nullptr, nullptr, q, DIM, DIM);
    gemm_mma<3><<<dim3(8, 128), 512, SMEM2>>>(h, wk, nullptr, nullptr, k, DIM, DIM);
    gemm_mma<3><<<dim3(8, 128), 512, SMEM2>>>(h, wv, nullptr, nullptr, v, DIM, DIM);
    qsm_kernel<<<(NBH*SEQ)/8, 256>>>(q);
    ksm_partial<<<dim3(KCH, NBH), 256>>>(k, part);
    ksm_norm   <<<dim3(KCH, NBH), 256>>>(k, part);
    ctx_gemm   <<<dim3(4, 4, NBH), 256>>>(k, v, ctx);
    gemm_mma<4><<<dim3(2, 32, NBH), 512, SMEM2>>>(q, ctx, nullptr, nullptr, attn, DH, DH);
    gemm_mma<1><<<dim3(8, 128), 512, SMEM2>>>(attn, wo, bo, x, x1, DIM, DIM);

    // --- FFN block ---
    ln_kernel<<<TOK, 256>>>(x1, ln2g, ln2b, h);
    gemm_mma<2><<<dim3(32, 128), 512, SMEM2>>>(h, wff1, bff1, nullptr, ff, FFD, DIM);
    gemm_mma<1><<<dim3(8, 128), 512, SMEM2>>>(ff, wff2, bff2, x1, x2, DIM, FFD);

    // --- trailing dense ---
    gemm_mma<0><<<dim3(8, 128), 512, SMEM2>>>(x2, wd, bd, nullptr, out, DIM, DIM);
}

// round 7
// speedup vs baseline: 1.7404x; 1.7404x over previous
#include <cuda_runtime.h>
#include <math.h>
#include <stdint.h>

#define BATCH 4
#define SEQ   4096
#define DIM   1024
#define NH    4
#define DH    256
#define FFD   4096
#define TOK   (BATCH*SEQ)   /* 16384 */
#define NBH   (BATCH*NH)    /* 16 */
#define KCH   16
#define CHUNK (SEQ/KCH)     /* 256 */

/* mma GEMM tiling: 128x128 CTA tile, 256 threads, 8 warps of 64x32 */
#define TM 128
#define TN 128
#define TK 32
#define APITCH 36
#define BPITCH 136
#define ABYTES (TM*APITCH*4)      /* 18432 */
#define BBYTES (TK*BPITCH*4)      /* 17408 */
#define SMEM2  (2*(ABYTES+BBYTES)) /* 71680 */

// ---------------- scratch ---------------------------------------------------
__device__ float g_h   [(size_t)TOK*DIM];
__device__ float g_q   [(size_t)NBH*SEQ*DH];
__device__ float g_k   [(size_t)NBH*SEQ*DH];
__device__ float g_v   [(size_t)NBH*SEQ*DH];
__device__ float g_ctx [(size_t)NBH*DH*DH];
__device__ float g_attn[(size_t)TOK*DIM];
__device__ float g_x1  [(size_t)TOK*DIM];
__device__ float g_x2  [(size_t)TOK*DIM];
__device__ float g_ff  [(size_t)TOK*FFD];
__device__ float g_part[NBH*KCH*2*DH];
__device__ float g_wr  [(size_t)13*1024*1024];   /* rounded weight copies */

/* offsets into g_wr (floats) */
#define OFF_WQ   (0)
#define OFF_WK   (1*1024*1024)
#define OFF_WV   (2*1024*1024)
#define OFF_WO   (3*1024*1024)
#define OFF_WD   (4*1024*1024)
#define OFF_WFF1 (5*1024*1024)
#define OFF_WFF2 (9*1024*1024)

__device__ __forceinline__ float gelu_tanh(float x) {
    float x3 = x*x*x;
    return 0.5f*x*(1.0f + tanhf(0.7978845608028654f*(x + 0.044715f*x3)));
}
__device__ __forceinline__ float rtf(float x) {     /* round-to-nearest tf32 */
    uint32_t u;
    asm("cvt.rna.tf32.f32 %0, %1;" : "=r"(u) : "f"(x));
    return __uint_as_float(u);
}
__device__ __forceinline__ uint32_t smem_u32(const void* p) {
    uint32_t a;
    asm("{ .reg .u64 t; cvta.to.shared.u64 t, %1; cvt.u32.u64 %0, t; }" : "=r"(a) : "l"(p));
    return a;
}
__device__ __forceinline__ void cp16(uint32_t dst, const void* src) {
    asm volatile("cp.async.cg.shared.global [%0], [%1], 16;" :: "r"(dst), "l"(src));
}
__device__ __forceinline__ void ldm_x4(uint32_t* r, uint32_t addr) {
    asm volatile("ldmatrix.sync.aligned.m8n8.x4.shared.b16 {%0,%1,%2,%3}, [%4];"
        : "=r"(r[0]), "=r"(r[1]), "=r"(r[2]), "=r"(r[3]) : "r"(addr));
}
__device__ __forceinline__ void mma_tf32(float* c, uint32_t a0, uint32_t a1, uint32_t a2,
                                         uint32_t a3, uint32_t b0, uint32_t b1) {
    asm volatile("mma.sync.aligned.m16n8k8.row.col.f32.tf32.tf32.f32 "
        "{%0,%1,%2,%3}, {%4,%5,%6,%7}, {%8,%9}, {%0,%1,%2,%3};"
        : "+f"(c[0]), "+f"(c[1]), "+f"(c[2]), "+f"(c[3])
        : "r"(a0), "r"(a1), "r"(a2), "r"(a3), "r"(b0), "r"(b1));
}

// ---------------- weight pre-rounding ---------------------------------------
__global__ void round_kernel(const float* __restrict__ src, float* __restrict__ dst, int n4)
{
    const int i = blockIdx.x * blockDim.x + threadIdx.x;
    if (i < n4) {
        float4 v = ((const float4*)src)[i];
        v.x = rtf(v.x); v.y = rtf(v.y); v.z = rtf(v.z); v.w = rtf(v.w);
        ((float4*)dst)[i] = v;
    }
}

// ---------------- mma.sync tf32 GEMM, 128x128 tiles, 256 threads ------------
// Operands must be pre-rounded to tf32 (RNA) by producers.
// MODE 0: C = acc + bias                      (exact out)
// MODE 1: C = acc + bias + res                (exact out)
// MODE 2: C = rtf(gelu(acc + bias))           (rounded out -> GEMM input)
// MODE 3: C = acc scattered to [b,h,n,dh]     (exact out)
// MODE 4: batched attn out, rounded, scatter to [b,n,d]
// MODE 5: C = rtf(acc + bias + res)           (rounded out -> GEMM input)
template<int MODE>
__global__ void __launch_bounds__(256, 2)
gemm_mma(const float* __restrict__ A, const float* __restrict__ W,
         const float* __restrict__ bias, const float* __restrict__ res,
         float* __restrict__ C, int Ncols, int K)
{
    extern __shared__ char dsm[];
    float* Bs[2] = { (float*)(dsm + 2*ABYTES),   (float*)(dsm + 2*ABYTES + BBYTES) };
    const uint32_t aAs[2] = { smem_u32(dsm), smem_u32(dsm + ABYTES) };
    const uint32_t aBs[2] = { smem_u32(Bs[0]), smem_u32(Bs[1]) };

    if (MODE == 4) {
        A += (size_t)blockIdx.z * SEQ * DH;
        W += (size_t)blockIdx.z * DH * DH;
    }

    const int tid  = threadIdx.x;
    const int lane = tid & 31;
    const int w    = tid >> 5;          /* 0..7 */
    const int m0w  = (w >> 2) * 64;     /* warp M offset in tile */
    const int n0w  = (w & 3) * 32;      /* warp N offset in tile */
    const int row0 = blockIdx.y * TM;
    const int col0 = blockIdx.x * TN;
    const int NT   = K / TK;

    const int lr = lane >> 2;           /* 0..7  */
    const int lc = lane & 3;            /* 0..3  */
    /* ldmatrix source row/col for the A x4 load (16x8 f32 tile) */
    const int lrow = (lane & 7) | (((lane >> 3) & 1) << 3);   /* 0..15 */
    const int lcol = (lane >> 4) * 4;                          /* 0 or 4 */

    auto fill = [&](int buf, int k0) {
        #pragma unroll
        for (int j = 0; j < 4; j++) {
            int f  = tid + 256*j;
            int r  = f >> 3, c4 = f & 7;
            cp16(aAs[buf] + (uint32_t)(r*APITCH + c4*4)*4,
                 A + (size_t)(row0 + r)*K + k0 + c4*4);
        }
        #pragma unroll
        for (int j = 0; j < 4; j++) {
            int f  = tid + 256*j;
            int kr = f >> 5, c4 = f & 31;
            cp16(aBs[buf] + (uint32_t)(kr*BPITCH + c4*4)*4,
                 W + (size_t)(k0 + kr)*Ncols + col0 + c4*4);
        }
        asm volatile("cp.async.commit_group;");
    };

    float acc[4][4][4];
    #pragma unroll
    for (int i = 0; i < 4; i++)
        #pragma unroll
        for (int j = 0; j < 4; j++)
            #pragma unroll
            for (int r = 0; r < 4; r++) acc[i][j][r] = 0.f;

    fill(0, 0);

    for (int t = 0; t < NT; t++) {
        if (t + 1 < NT) {
            fill((t + 1) & 1, (t + 1) * TK);
            asm volatile("cp.async.wait_group 1;");
        } else {
            asm volatile("cp.async.wait_group 0;");
        }
        __syncthreads();

        const uint32_t aab = aAs[t & 1];
        const float*   Bb  = Bs[t & 1];
        const uint32_t a_lm = aab + (uint32_t)((m0w + lrow)*APITCH + lcol)*4;

        #pragma unroll
        for (int kk = 0; kk < 4; kk++) {
            uint32_t af[4][4];
            #pragma unroll
            for (int mf = 0; mf < 4; mf++)
                ldm_x4(af[mf], a_lm + (uint32_t)(mf*16*APITCH + kk*8)*4);

            uint32_t bf[4][2];
            const float* bp0 = Bb + (kk*8 + lc)*BPITCH + n0w + lr;
            #pragma unroll
            for (int nf = 0; nf < 4; nf++) {
                bf[nf][0] = __float_as_uint(bp0[nf*8]);
                bf[nf][1] = __float_as_uint(bp0[nf*8 + 4*BPITCH]);
            }
            #pragma unroll
            for (int mf = 0; mf < 4; mf++)
                #pragma unroll
                for (int nf = 0; nf < 4; nf++)
                    mma_tf32(acc[mf][nf], af[mf][0], af[mf][1], af[mf][2], af[mf][3],
                             bf[nf][0], bf[nf][1]);
        }
        __syncthreads();
    }

    // ---- epilogue ----
    #pragma unroll
    for (int mf = 0; mf < 4; mf++) {
        #pragma unroll
        for (int half = 0; half < 2; half++) {
            const int grow = row0 + m0w + mf*16 + lr + half*8;
            #pragma unroll
            for (int nf = 0; nf < 4; nf++) {
                const int gcol = col0 + n0w + nf*8 + 2*lc;
                float v0 = acc[mf][nf][half*2 + 0];
                float v1 = acc[mf][nf][half*2 + 1];
                if (MODE == 3) {
                    const int head = gcol >> 8;
                    const int dh0  = gcol & 255;
                    const int b_   = grow >> 12;
                    const int n_   = grow & 4095;
                    float* op = C + ((size_t)((b_*NH + head)*SEQ + n_))*DH + dh0;
                    *(float2*)op = make_float2(v0, v1);
                } else if (MODE == 4) {
                    const int b_   = blockIdx.z >> 2;
                    const int head = blockIdx.z & 3;
                    float* op = C + ((size_t)(b_*SEQ + grow))*DIM + head*DH + gcol;
                    *(float2*)op = make_float2(rtf(v0), rtf(v1));
                } else {
                    v0 += bias[gcol];
                    v1 += bias[gcol + 1];
                    if (MODE == 2) { v0 = gelu_tanh(v0); v1 = gelu_tanh(v1); }
                    if (MODE == 1 || MODE == 5) {
                        const float2 rv = *(const float2*)(res + (size_t)grow*Ncols + gcol);
                        v0 += rv.x; v1 += rv.y;
                    }
                    if (MODE == 2 || MODE == 5) { v0 = rtf(v0); v1 = rtf(v1); }
                    *(float2*)(C + (size_t)grow*Ncols + gcol) = make_float2(v0, v1);
                }
            }
        }
    }
}

// ---------------- LayerNorm (output rounded to tf32: feeds GEMMs only) ------
__global__ void ln_kernel(const float* __restrict__ x, const float* __restrict__ g,
                          const float* __restrict__ b, float* __restrict__ out)
{
    __shared__ float red[16];
    __shared__ float s_mu, s_rstd;
    const int row = blockIdx.x, t = threadIdx.x;
    const float4 v = ((const float4*)(x + (size_t)row*DIM))[t];
    float s  = v.x + v.y + v.z + v.w;
    float ss = fmaf(v.x,v.x, fmaf(v.y,v.y, fmaf(v.z,v.z, v.w*v.w)));
    #pragma unroll
    for (int o = 16; o > 0; o >>= 1) {
        s  += __shfl_xor_sync(0xffffffffu, s,  o);
        ss += __shfl_xor_sync(0xffffffffu, ss, o);
    }
    const int w = t >> 5, lane = t & 31;
    if (lane == 0) { red[w] = s; red[8+w] = ss; }
    __syncthreads();
    if (t == 0) {
        float S = 0.f, SS = 0.f;
        #pragma unroll
        for (int i = 0; i < 8; i++) { S += red[i]; SS += red[8+i]; }
        float mu  = S  * (1.0f/DIM);
        float var = SS * (1.0f/DIM) - mu*mu;
        s_mu = mu; s_rstd = rsqrtf(var + 1e-5f);
    }
    __syncthreads();
    const float mu = s_mu, r = s_rstd;
    const float4 gv = ((const float4*)g)[t];
    const float4 bv = ((const float4*)b)[t];
    float4 o;
    o.x = rtf((v.x-mu)*r*gv.x + bv.x);
    o.y = rtf((v.y-mu)*r*gv.y + bv.y);
    o.z = rtf((v.z-mu)*r*gv.z + bv.z);
    o.w = rtf((v.w-mu)*r*gv.w + bv.w);
    ((float4*)(out + (size_t)row*DIM))[t] = o;
}

// ---------------- q softmax over head dim (output rounded) ------------------
__global__ void qsm_kernel(float* __restrict__ q)
{
    const int warp = (blockIdx.x * blockDim.x + threadIdx.x) >> 5;
    const int lane = threadIdx.x & 31;
    float* row = q + (size_t)warp * DH;
    float v[8];
    float m = -INFINITY;
    #pragma unroll
    for (int j = 0; j < 8; j++) { v[j] = row[j*32 + lane] * 0.25f; m = fmaxf(m, v[j]); }
    #pragma unroll
    for (int o = 16; o > 0; o >>= 1) m = fmaxf(m, __shfl_xor_sync(0xffffffffu, m, o));
    float s = 0.f;
    #pragma unroll
    for (int j = 0; j < 8; j++) { v[j] = expf(v[j] - m); s += v[j]; }
    #pragma unroll
    for (int o = 16; o > 0; o >>= 1) s += __shfl_xor_sync(0xffffffffu, s, o);
    const float inv = 1.0f / s;
    #pragma unroll
    for (int j = 0; j < 8; j++) row[j*32 + lane] = rtf(v[j] * inv);
}

// ---------------- k softmax over sequence dim (2-pass chunked) --------------
__global__ void ksm_partial(const float* __restrict__ k, float* __restrict__ part)
{
    const int bh = blockIdx.y, ch = blockIdx.x, t = threadIdx.x;
    const float* kp = k + ((size_t)bh*SEQ + (size_t)ch*CHUNK)*DH + t;
    float m = -INFINITY, s = 0.f;
    for (int i = 0; i < CHUNK; i++) {
        const float vv = kp[(size_t)i*DH] * 0.25f;
        const float nm = fmaxf(m, vv);
        s = s*expf(m - nm) + expf(vv - nm);
        m = nm;
    }
    float* pp = part + (size_t)((bh*KCH + ch)*2)*DH;
    pp[t] = m; pp[DH + t] = s;
}

__global__ void ksm_norm(float* __restrict__ k, const float* __restrict__ part)
{
    const int bh = blockIdx.y, ch = blockIdx.x, t = threadIdx.x;
    float M = -INFINITY;
    #pragma unroll
    for (int c = 0; c < KCH; c++)
        M = fmaxf(M, part[(size_t)((bh*KCH + c)*2)*DH + t]);
    float S = 0.f;
    #pragma unroll
    for (int c = 0; c < KCH; c++) {
        const float* pp = part + (size_t)((bh*KCH + c)*2)*DH;
        S += pp[DH + t] * expf(pp[t] - M);
    }
    const float inv = 1.0f / S;
    float* kp = k + ((size_t)bh*SEQ + (size_t)ch*CHUNK)*DH + t;
    for (int i = 0; i < CHUNK; i++) {
        const float vv = kp[(size_t)i*DH] * 0.25f;
        kp[(size_t)i*DH] = expf(vv - M) * inv;
    }
}

// ---------------- ctx = k^T @ v, fp32 SIMT, output rounded ------------------
__global__ void __launch_bounds__(256)
ctx_gemm(const float* __restrict__ k, const float* __restrict__ v, float* __restrict__ ctx)
{
    __shared__ float As[16][64];
    __shared__ float Bs[16][64];
    const int bh = blockIdx.z;
    const int m0 = blockIdx.y * 64, e0 = blockIdx.x * 64;
    const int tid = threadIdx.x;
    const int tx = tid & 15, ty = tid >> 4;
    const int lr = tid >> 4;
    const int lc = (tid & 15) * 4;
    const float* kb = k + (size_t)bh*SEQ*DH;
    const float* vb = v + (size_t)bh*SEQ*DH;
    float acc[4][4] = {};

    for (int n0 = 0; n0 < SEQ; n0 += 16) {
        *(float4*)&As[lr][lc] = *(const float4*)(kb + (size_t)(n0+lr)*DH + m0 + lc);
        *(float4*)&Bs[lr][lc] = *(const float4*)(vb + (size_t)(n0+lr)*DH + e0 + lc);
        __syncthreads();
        #pragma unroll
        for (int kk = 0; kk < 16; kk++) {
            float4 a = *(const float4*)&As[kk][ty*4];
            float4 b = *(const float4*)&Bs[kk][tx*4];
            const float ar[4] = {a.x,a.y,a.z,a.w};
            const float br[4] = {b.x,b.y,b.z,b.w};
            #pragma unroll
            for (int i = 0; i < 4; i++)
                #pragma unroll
                for (int j = 0; j < 4; j++)
                    acc[i][j] = fmaf(ar[i], br[j], acc[i][j]);
        }
        __syncthreads();
    }
    float* cb = ctx + (size_t)bh*DH*DH;
    #pragma unroll
    for (int i = 0; i < 4; i++)
        *(float4*)(cb + (size_t)(m0 + ty*4 + i)*DH + e0 + tx*4) =
            make_float4(rtf(acc[i][0]), rtf(acc[i][1]), rtf(acc[i][2]), rtf(acc[i][3]));
}

// ---------------- launch ----------------------------------------------------
extern "C" void kernel_launch(void* const* d_in, const int* in_sizes, int n_in,
                              void* d_out, int out_size)
{
    const float* x    = (const float*)d_in[0];
    const float* ln1g = (const float*)d_in[1];
    const float* ln1b = (const float*)d_in[2];
    const float* wq   = (const float*)d_in[3];
    const float* wk   = (const float*)d_in[4];
    const float* wv   = (const float*)d_in[5];
    const float* wo   = (const float*)d_in[6];
    const float* bo   = (const float*)d_in[7];
    const float* ln2g = (const float*)d_in[8];
    const float* ln2b = (const float*)d_in[9];
    const float* wff1 = (const float*)d_in[10];
    const float* bff1 = (const float*)d_in[11];
    const float* wff2 = (const float*)d_in[12];
    const float* bff2 = (const float*)d_in[13];
    const float* wd   = (const float*)d_in[14];
    const float* bd   = (const float*)d_in[15];
    float* out = (float*)d_out;

    float *h,*q,*k,*v,*ctx,*attn,*x1,*x2,*ff,*part,*wr;
    cudaGetSymbolAddress((void**)&h,    g_h);
    cudaGetSymbolAddress((void**)&q,    g_q);
    cudaGetSymbolAddress((void**)&k,    g_k);
    cudaGetSymbolAddress((void**)&v,    g_v);
    cudaGetSymbolAddress((void**)&ctx,  g_ctx);
    cudaGetSymbolAddress((void**)&attn, g_attn);
    cudaGetSymbolAddress((void**)&x1,   g_x1);
    cudaGetSymbolAddress((void**)&x2,   g_x2);
    cudaGetSymbolAddress((void**)&ff,   g_ff);
    cudaGetSymbolAddress((void**)&part, g_part);
    cudaGetSymbolAddress((void**)&wr,   g_wr);

    cudaFuncSetAttribute(gemm_mma<0>, cudaFuncAttributeMaxDynamicSharedMemorySize, SMEM2);
    cudaFuncSetAttribute(gemm_mma<1>, cudaFuncAttributeMaxDynamicSharedMemorySize, SMEM2);
    cudaFuncSetAttribute(gemm_mma<2>, cudaFuncAttributeMaxDynamicSharedMemorySize, SMEM2);
    cudaFuncSetAttribute(gemm_mma<3>, cudaFuncAttributeMaxDynamicSharedMemorySize, SMEM2);
    cudaFuncSetAttribute(gemm_mma<4>, cudaFuncAttributeMaxDynamicSharedMemorySize, SMEM2);
    cudaFuncSetAttribute(gemm_mma<5>, cudaFuncAttributeMaxDynamicSharedMemorySize, SMEM2);

    // --- pre-round weights into scratch (RNA to tf32) ---
    const int n4_d  = DIM*DIM/4;     /* 262144 */
    const int n4_ff = DIM*FFD/4;     /* 1048576 */
    round_kernel<<<n4_d/256, 256>>>(wq,   wr + OFF_WQ,   n4_d);
    round_kernel<<<n4_d/256, 256>>>(wk,   wr + OFF_WK,   n4_d);
    round_kernel<<<n4_d/256, 256>>>(wv,   wr + OFF_WV,   n4_d);
    round_kernel<<<n4_d/256, 256>>>(wo,   wr + OFF_WO,   n4_d);
    round_kernel<<<n4_d/256, 256>>>(wd,   wr + OFF_WD,   n4_d);
    round_kernel<<<n4_ff/256, 256>>>(wff1, wr + OFF_WFF1, n4_ff);
    round_kernel<<<n4_ff/256, 256>>>(wff2, wr + OFF_WFF2, n4_ff);

    // --- attention block ---
    ln_kernel<<<TOK, 256>>>(x, ln1g, ln1b, h);
    gemm_mma<3><<<dim3(8, 128), 256, SMEM2>>>(h, wr + OFF_WQ, nullptr, nullptr, q, DIM, DIM);
    gemm_mma<3><<<dim3(8, 128), 256, SMEM2>>>(h, wr + OFF_WK, nullptr, nullptr, k, DIM, DIM);
    gemm_mma<3><<<dim3(8, 128), 256, SMEM2>>>(h, wr + OFF_WV, nullptr, nullptr, v, DIM, DIM);
    qsm_kernel<<<(NBH*SEQ)/8, 256>>>(q);
    ksm_partial<<<dim3(KCH, NBH), 256>>>(k, part);
    ksm_norm   <<<dim3(KCH, NBH), 256>>>(k, part);
    ctx_gemm   <<<dim3(4, 4, NBH), 256>>>(k, v, ctx);
    gemm_mma<4><<<dim3(2, 32, NBH), 256, SMEM2>>>(q, ctx, nullptr, nullptr, attn, DH, DH);
    gemm_mma<1><<<dim3(8, 128), 256, SMEM2>>>(attn, wr + OFF_WO, bo, x, x1, DIM, DIM);

    // --- FFN block ---
    ln_kernel<<<TOK, 256>>>(x1, ln2g, ln2b, h);
    gemm_mma<2><<<dim3(32, 128), 256, SMEM2>>>(h, wr + OFF_WFF1, bff1, nullptr, ff, FFD, DIM);
    gemm_mma<5><<<dim3(8, 128), 256, SMEM2>>>(ff, wr + OFF_WFF2, bff2, x1, x2, DIM, FFD);

    // --- trailing dense ---
    gemm_mma<0><<<dim3(8, 128), 256, SMEM2>>>(x2, wr + OFF_WD, bd, nullptr, out, DIM, DIM);
}

// round 8
// speedup vs baseline: 2.9523x; 1.6963x over previous
#include <cuda_runtime.h>
#include <cuda_fp16.h>
#include <math.h>
#include <stdint.h>

#define BATCH 4
#define SEQ   4096
#define DIM   1024
#define NH    4
#define DH    256
#define FFD   4096
#define TOK   (BATCH*SEQ)   /* 16384 */
#define NBH   (BATCH*NH)    /* 16 */
#define KCH   16
#define CHUNK (SEQ/KCH)     /* 256 */

/* fp16 mma GEMM tiling: 128x128 CTA tile, 256 threads, 8 warps of 64x32 */
#define TM 128
#define TN 128
#define TK 64                       /* K halves per smem tile */
#define APITCH 72                   /* halves: 144B row stride, ldmatrix conflict-free */
#define BPITCH 136                  /* halves: 272B row stride, conflict-free */
#define ABYTES (TM*APITCH*2)        /* 18432 */
#define BBYTES (TK*BPITCH*2)        /* 17408 */
#define SMEM2  (2*(ABYTES+BBYTES))  /* 71680 */

// ---------------- scratch ---------------------------------------------------
__device__ float  g_q   [(size_t)NBH*SEQ*DH];
__device__ float  g_k   [(size_t)NBH*SEQ*DH];
__device__ float  g_v   [(size_t)NBH*SEQ*DH];
__device__ float  g_x1  [(size_t)TOK*DIM];
__device__ float  g_part[NBH*KCH*2*DH];
__device__ __half g_h   [(size_t)TOK*DIM];
__device__ __half g_qh  [(size_t)NBH*SEQ*DH];
__device__ __half g_ctxh[(size_t)NBH*DH*DH];
__device__ __half g_attnh[(size_t)TOK*DIM];
__device__ __half g_ffh [(size_t)TOK*FFD];
__device__ __half g_x2h [(size_t)TOK*DIM];
__device__ __half g_wr  [(size_t)13*1024*1024];

/* offsets into g_wr (halves) */
#define OFF_WQ   (0)
#define OFF_WK   (1*1024*1024)
#define OFF_WV   (2*1024*1024)
#define OFF_WO   (3*1024*1024)
#define OFF_WD   (4*1024*1024)
#define OFF_WFF1 (5*1024*1024)
#define OFF_WFF2 (9*1024*1024)

__device__ __forceinline__ float gelu_tanh(float x) {
    float x3 = x*x*x;
    return 0.5f*x*(1.0f + tanhf(0.7978845608028654f*(x + 0.044715f*x3)));
}
__device__ __forceinline__ uint32_t smem_u32(const void* p) {
    uint32_t a;
    asm("{ .reg .u64 t; cvta.to.shared.u64 t, %1; cvt.u32.u64 %0, t; }" : "=r"(a) : "l"(p));
    return a;
}
__device__ __forceinline__ void cp16(uint32_t dst, const void* src) {
    asm volatile("cp.async.cg.shared.global [%0], [%1], 16;" :: "r"(dst), "l"(src));
}
__device__ __forceinline__ void ldm_x4(uint32_t* r, uint32_t addr) {
    asm volatile("ldmatrix.sync.aligned.m8n8.x4.shared.b16 {%0,%1,%2,%3}, [%4];"
        : "=r"(r[0]), "=r"(r[1]), "=r"(r[2]), "=r"(r[3]) : "r"(addr));
}
__device__ __forceinline__ void ldm_x4_t(uint32_t* r, uint32_t addr) {
    asm volatile("ldmatrix.sync.aligned.m8n8.x4.trans.shared.b16 {%0,%1,%2,%3}, [%4];"
        : "=r"(r[0]), "=r"(r[1]), "=r"(r[2]), "=r"(r[3]) : "r"(addr));
}
__device__ __forceinline__ void mma_f16(float* c, uint32_t a0, uint32_t a1, uint32_t a2,
                                        uint32_t a3, uint32_t b0, uint32_t b1) {
    asm volatile("mma.sync.aligned.m16n8k16.row.col.f32.f16.f16.f32 "
        "{%0,%1,%2,%3}, {%4,%5,%6,%7}, {%8,%9}, {%0,%1,%2,%3};"
        : "+f"(c[0]), "+f"(c[1]), "+f"(c[2]), "+f"(c[3])
        : "r"(a0), "r"(a1), "r"(a2), "r"(a3), "r"(b0), "r"(b1));
}

// ---------------- weight fp32 -> fp16 conversion -----------------------------
__global__ void cvt_kernel(const float* __restrict__ src, __half* __restrict__ dst, int n4)
{
    const int i = blockIdx.x * blockDim.x + threadIdx.x;
    if (i < n4) {
        float4 v = ((const float4*)src)[i];
        __half2* d2 = (__half2*)dst;
        d2[2*i]   = __floats2half2_rn(v.x, v.y);
        d2[2*i+1] = __floats2half2_rn(v.z, v.w);
    }
}

// ---------------- fp16 mma GEMM, 128x128 tiles, 256 threads ------------------
// MODE 0: C(fp32) = acc + bias
// MODE 1: C(fp32) = acc + bias + res
// MODE 2: C(fp16) = gelu(acc + bias)
// MODE 3: C(fp32) = acc scattered to [b,h,n,dh]
// MODE 4: batched attn out: A=qh+z*SEQ*DH, W=ctxh+z*DH*DH, C(fp16) scatter [b,n,d]
// MODE 5: C(fp16) = acc + bias + res
template<int MODE>
__global__ void __launch_bounds__(256, 2)
gemm_mma(const __half* __restrict__ A, const __half* __restrict__ W,
         const float* __restrict__ bias, const float* __restrict__ res,
         void* __restrict__ Cv, int Ncols, int K)
{
    extern __shared__ char dsm[];
    const uint32_t aAs[2] = { smem_u32(dsm), smem_u32(dsm + ABYTES) };
    const uint32_t aBs[2] = { smem_u32(dsm + 2*ABYTES), smem_u32(dsm + 2*ABYTES + BBYTES) };

    if (MODE == 4) {
        A += (size_t)blockIdx.z * SEQ * DH;
        W += (size_t)blockIdx.z * DH * DH;
    }

    const int tid  = threadIdx.x;
    const int lane = tid & 31;
    const int w    = tid >> 5;          /* 0..7 */
    const int m0w  = (w >> 2) * 64;
    const int n0w  = (w & 3) * 32;
    const int row0 = blockIdx.y * TM;
    const int col0 = blockIdx.x * TN;
    const int NT   = K / TK;

    const int lr = lane >> 2;           /* 0..7 */
    const int lc = lane & 3;            /* 0..3 */
    const int l15 = lane & 15;
    const int lhi8 = (lane >> 4) * 8;

    auto fill = [&](int buf, int k0) {
        /* A: 128 rows x 64 halves -> 1024 x 16B, 4 per thread */
        #pragma unroll
        for (int j = 0; j < 4; j++) {
            int f  = tid + 256*j;
            int r  = f >> 3, c8 = f & 7;
            cp16(aAs[buf] + (uint32_t)(r*APITCH + c8*8)*2,
                 A + (size_t)(row0 + r)*K + k0 + c8*8);
        }
        /* B: 64 rows x 128 halves -> 1024 x 16B, 4 per thread */
        #pragma unroll
        for (int j = 0; j < 4; j++) {
            int f  = tid + 256*j;
            int kr = f >> 4, c8 = f & 15;
            cp16(aBs[buf] + (uint32_t)(kr*BPITCH + c8*8)*2,
                 W + (size_t)(k0 + kr)*Ncols + col0 + c8*8);
        }
        asm volatile("cp.async.commit_group;");
    };

    float acc[4][4][4];
    #pragma unroll
    for (int i = 0; i < 4; i++)
        #pragma unroll
        for (int j = 0; j < 4; j++)
            #pragma unroll
            for (int r = 0; r < 4; r++) acc[i][j][r] = 0.f;

    fill(0, 0);

    for (int t = 0; t < NT; t++) {
        if (t + 1 < NT) {
            fill((t + 1) & 1, (t + 1) * TK);
            asm volatile("cp.async.wait_group 1;");
        } else {
            asm volatile("cp.async.wait_group 0;");
        }
        __syncthreads();

        /* per-thread ldmatrix base addresses */
        const uint32_t a_lm = aAs[t & 1] + (uint32_t)((m0w + l15)*APITCH + lhi8)*2;
        const uint32_t b_lm = aBs[t & 1] + (uint32_t)(l15*BPITCH + n0w + lhi8)*2;

        #pragma unroll
        for (int kk = 0; kk < 4; kk++) {
            uint32_t af[4][4];
            #pragma unroll
            for (int mf = 0; mf < 4; mf++)
                ldm_x4(af[mf], a_lm + (uint32_t)(mf*16*APITCH + kk*16)*2);

            uint32_t bf[2][4];
            #pragma unroll
            for (int np = 0; np < 2; np++)
                ldm_x4_t(bf[np], b_lm + (uint32_t)(kk*16*BPITCH + np*16)*2);

            #pragma unroll
            for (int mf = 0; mf < 4; mf++)
                #pragma unroll
                for (int nf = 0; nf < 4; nf++)
                    mma_f16(acc[mf][nf],
                            af[mf][0], af[mf][1], af[mf][2], af[mf][3],
                            bf[nf >> 1][(nf & 1)*2], bf[nf >> 1][(nf & 1)*2 + 1]);
        }
        __syncthreads();
    }

    // ---- epilogue ----
    float*  Cf = (float*)Cv;
    __half* Ch = (__half*)Cv;
    #pragma unroll
    for (int mf = 0; mf < 4; mf++) {
        #pragma unroll
        for (int half_ = 0; half_ < 2; half_++) {
            const int grow = row0 + m0w + mf*16 + lr + half_*8;
            #pragma unroll
            for (int nf = 0; nf < 4; nf++) {
                const int gcol = col0 + n0w + nf*8 + 2*lc;
                float v0 = acc[mf][nf][half_*2 + 0];
                float v1 = acc[mf][nf][half_*2 + 1];
                if (MODE == 3) {
                    const int head = gcol >> 8;
                    const int dh0  = gcol & 255;
                    const int b_   = grow >> 12;
                    const int n_   = grow & 4095;
                    float* op = Cf + ((size_t)((b_*NH + head)*SEQ + n_))*DH + dh0;
                    *(float2*)op = make_float2(v0, v1);
                } else if (MODE == 4) {
                    const int b_   = blockIdx.z >> 2;
                    const int head = blockIdx.z & 3;
                    __half2* op = (__half2*)(Ch + ((size_t)(b_*SEQ + grow))*DIM + head*DH + gcol);
                    *op = __floats2half2_rn(v0, v1);
                } else {
                    v0 += bias[gcol];
                    v1 += bias[gcol + 1];
                    if (MODE == 2) { v0 = gelu_tanh(v0); v1 = gelu_tanh(v1); }
                    if (MODE == 1 || MODE == 5) {
                        const float2 rv = *(const float2*)(res + (size_t)grow*Ncols + gcol);
                        v0 += rv.x; v1 += rv.y;
                    }
                    if (MODE == 2 || MODE == 5) {
                        *(__half2*)(Ch + (size_t)grow*Ncols + gcol) = __floats2half2_rn(v0, v1);
                    } else {
                        *(float2*)(Cf + (size_t)grow*Ncols + gcol) = make_float2(v0, v1);
                    }
                }
            }
        }
    }
}

// ---------------- LayerNorm (fp32 in, fp16 out: feeds GEMMs only) -----------
__global__ void ln_kernel(const float* __restrict__ x, const float* __restrict__ g,
                          const float* __restrict__ b, __half* __restrict__ out)
{
    __shared__ float red[16];
    __shared__ float s_mu, s_rstd;
    const int row = blockIdx.x, t = threadIdx.x;
    const float4 v = ((const float4*)(x + (size_t)row*DIM))[t];
    float s  = v.x + v.y + v.z + v.w;
    float ss = fmaf(v.x,v.x, fmaf(v.y,v.y, fmaf(v.z,v.z, v.w*v.w)));
    #pragma unroll
    for (int o = 16; o > 0; o >>= 1) {
        s  += __shfl_xor_sync(0xffffffffu, s,  o);
        ss += __shfl_xor_sync(0xffffffffu, ss, o);
    }
    const int w = t >> 5, lane = t & 31;
    if (lane == 0) { red[w] = s; red[8+w] = ss; }
    __syncthreads();
    if (t == 0) {
        float S = 0.f, SS = 0.f;
        #pragma unroll
        for (int i = 0; i < 8; i++) { S += red[i]; SS += red[8+i]; }
        float mu  = S  * (1.0f/DIM);
        float var = SS * (1.0f/DIM) - mu*mu;
        s_mu = mu; s_rstd = rsqrtf(var + 1e-5f);
    }
    __syncthreads();
    const float mu = s_mu, r = s_rstd;
    const float4 gv = ((const float4*)g)[t];
    const float4 bv = ((const float4*)b)[t];
    __half2* o2 = (__half2*)(out + (size_t)row*DIM);
    o2[t*2]   = __floats2half2_rn((v.x-mu)*r*gv.x + bv.x, (v.y-mu)*r*gv.y + bv.y);
    o2[t*2+1] = __floats2half2_rn((v.z-mu)*r*gv.z + bv.z, (v.w-mu)*r*gv.w + bv.w);
}

// ---------------- q softmax over head dim (fp32 in, fp16 out) ---------------
__global__ void qsm_kernel(const float* __restrict__ q, __half* __restrict__ qh)
{
    const int warp = (blockIdx.x * blockDim.x + threadIdx.x) >> 5;
    const int lane = threadIdx.x & 31;
    const float* row = q + (size_t)warp * DH;
    __half* rowh = qh + (size_t)warp * DH;
    float v[8];
    float m = -INFINITY;
    #pragma unroll
    for (int j = 0; j < 8; j++) { v[j] = row[j*32 + lane] * 0.25f; m = fmaxf(m, v[j]); }
    #pragma unroll
    for (int o = 16; o > 0; o >>= 1) m = fmaxf(m, __shfl_xor_sync(0xffffffffu, m, o));
    float s = 0.f;
    #pragma unroll
    for (int j = 0; j < 8; j++) { v[j] = expf(v[j] - m); s += v[j]; }
    #pragma unroll
    for (int o = 16; o > 0; o >>= 1) s += __shfl_xor_sync(0xffffffffu, s, o);
    const float inv = 1.0f / s;
    #pragma unroll
    for (int j = 0; j < 8; j++) rowh[j*32 + lane] = __float2half_rn(v[j] * inv);
}

// ---------------- k softmax over sequence dim (2-pass chunked, fp32) --------
__global__ void ksm_partial(const float* __restrict__ k, float* __restrict__ part)
{
    const int bh = blockIdx.y, ch = blockIdx.x, t = threadIdx.x;
    const float* kp = k + ((size_t)bh*SEQ + (size_t)ch*CHUNK)*DH + t;
    float m = -INFINITY, s = 0.f;
    for (int i = 0; i < CHUNK; i++) {
        const float vv = kp[(size_t)i*DH] * 0.25f;
        const float nm = fmaxf(m, vv);
        s = s*expf(m - nm) + expf(vv - nm);
        m = nm;
    }
    float* pp = part + (size_t)((bh*KCH + ch)*2)*DH;
    pp[t] = m; pp[DH + t] = s;
}

__global__ void ksm_norm(float* __restrict__ k, const float* __restrict__ part)
{
    const int bh = blockIdx.y, ch = blockIdx.x, t = threadIdx.x;
    float M = -INFINITY;
    #pragma unroll
    for (int c = 0; c < KCH; c++)
        M = fmaxf(M, part[(size_t)((bh*KCH + c)*2)*DH + t]);
    float S = 0.f;
    #pragma unroll
    for (int c = 0; c < KCH; c++) {
        const float* pp = part + (size_t)((bh*KCH + c)*2)*DH;
        S += pp[DH + t] * expf(pp[t] - M);
    }
    const float inv = 1.0f / S;
    float* kp = k + ((size_t)bh*SEQ + (size_t)ch*CHUNK)*DH + t;
    for (int i = 0; i < CHUNK; i++) {
        const float vv = kp[(size_t)i*DH] * 0.25f;
        kp[(size_t)i*DH] = expf(vv - M) * inv;
    }
}

// ---------------- ctx = k^T @ v, fp32 SIMT, fp16 out ------------------------
__global__ void __launch_bounds__(256)
ctx_gemm(const float* __restrict__ k, const float* __restrict__ v, __half* __restrict__ ctx)
{
    __shared__ float As[16][64];
    __shared__ float Bs[16][64];
    const int bh = blockIdx.z;
    const int m0 = blockIdx.y * 64, e0 = blockIdx.x * 64;
    const int tid = threadIdx.x;
    const int tx = tid & 15, ty = tid >> 4;
    const int lr = tid >> 4;
    const int lc = (tid & 15) * 4;
    const float* kb = k + (size_t)bh*SEQ*DH;
    const float* vb = v + (size_t)bh*SEQ*DH;
    float acc[4][4] = {};

    for (int n0 = 0; n0 < SEQ; n0 += 16) {
        *(float4*)&As[lr][lc] = *(const float4*)(kb + (size_t)(n0+lr)*DH + m0 + lc);
        *(float4*)&Bs[lr][lc] = *(const float4*)(vb + (size_t)(n0+lr)*DH + e0 + lc);
        __syncthreads();
        #pragma unroll
        for (int kk = 0; kk < 16; kk++) {
            float4 a = *(const float4*)&As[kk][ty*4];
            float4 b = *(const float4*)&Bs[kk][tx*4];
            const float ar[4] = {a.x,a.y,a.z,a.w};
            const float br[4] = {b.x,b.y,b.z,b.w};
            #pragma unroll
            for (int i = 0; i < 4; i++)
                #pragma unroll
                for (int j = 0; j < 4; j++)
                    acc[i][j] = fmaf(ar[i], br[j], acc[i][j]);
        }
        __syncthreads();
    }
    __half* cb = ctx + (size_t)bh*DH*DH;
    #pragma unroll
    for (int i = 0; i < 4; i++) {
        __half2* op = (__half2*)(cb + (size_t)(m0 + ty*4 + i)*DH + e0 + tx*4);
        op[0] = __floats2half2_rn(acc[i][0], acc[i][1]);
        op[1] = __floats2half2_rn(acc[i][2], acc[i][3]);
    }
}

// ---------------- launch ----------------------------------------------------
extern "C" void kernel_launch(void* const* d_in, const int* in_sizes, int n_in,
                              void* d_out, int out_size)
{
    const float* x    = (const float*)d_in[0];
    const float* ln1g = (const float*)d_in[1];
    const float* ln1b = (const float*)d_in[2];
    const float* wq   = (const float*)d_in[3];
    const float* wk   = (const float*)d_in[4];
    const float* wv   = (const float*)d_in[5];
    const float* wo   = (const float*)d_in[6];
    const float* bo   = (const float*)d_in[7];
    const float* ln2g = (const float*)d_in[8];
    const float* ln2b = (const float*)d_in[9];
    const float* wff1 = (const float*)d_in[10];
    const float* bff1 = (const float*)d_in[11];
    const float* wff2 = (const float*)d_in[12];
    const float* bff2 = (const float*)d_in[13];
    const float* wd   = (const float*)d_in[14];
    const float* bd   = (const float*)d_in[15];
    float* out = (float*)d_out;

    float *q,*k,*v,*x1,*part;
    __half *h,*qh,*ctxh,*attnh,*ffh,*x2h,*wr;
    cudaGetSymbolAddress((void**)&q,    g_q);
    cudaGetSymbolAddress((void**)&k,    g_k);
    cudaGetSymbolAddress((void**)&v,    g_v);
    cudaGetSymbolAddress((void**)&x1,   g_x1);
    cudaGetSymbolAddress((void**)&part, g_part);
    cudaGetSymbolAddress((void**)&h,    g_h);
    cudaGetSymbolAddress((void**)&qh,   g_qh);
    cudaGetSymbolAddress((void**)&ctxh, g_ctxh);
    cudaGetSymbolAddress((void**)&attnh,g_attnh);
    cudaGetSymbolAddress((void**)&ffh,  g_ffh);
    cudaGetSymbolAddress((void**)&x2h,  g_x2h);
    cudaGetSymbolAddress((void**)&wr,   g_wr);

    cudaFuncSetAttribute(gemm_mma<0>, cudaFuncAttributeMaxDynamicSharedMemorySize, SMEM2);
    cudaFuncSetAttribute(gemm_mma<1>, cudaFuncAttributeMaxDynamicSharedMemorySize, SMEM2);
    cudaFuncSetAttribute(gemm_mma<2>, cudaFuncAttributeMaxDynamicSharedMemorySize, SMEM2);
    cudaFuncSetAttribute(gemm_mma<3>, cudaFuncAttributeMaxDynamicSharedMemorySize, SMEM2);
    cudaFuncSetAttribute(gemm_mma<4>, cudaFuncAttributeMaxDynamicSharedMemorySize, SMEM2);
    cudaFuncSetAttribute(gemm_mma<5>, cudaFuncAttributeMaxDynamicSharedMemorySize, SMEM2);

    // --- convert weights to fp16 ---
    const int n4_d  = DIM*DIM/4;
    const int n4_ff = DIM*FFD/4;
    cvt_kernel<<<n4_d/256, 256>>>(wq,   wr + OFF_WQ,   n4_d);
    cvt_kernel<<<n4_d/256, 256>>>(wk,   wr + OFF_WK,   n4_d);
    cvt_kernel<<<n4_d/256, 256>>>(wv,   wr + OFF_WV,   n4_d);
    cvt_kernel<<<n4_d/256, 256>>>(wo,   wr + OFF_WO,   n4_d);
    cvt_kernel<<<n4_d/256, 256>>>(wd,   wr + OFF_WD,   n4_d);
    cvt_kernel<<<n4_ff/256, 256>>>(wff1, wr + OFF_WFF1, n4_ff);
    cvt_kernel<<<n4_ff/256, 256>>>(wff2, wr + OFF_WFF2, n4_ff);

    // --- attention block ---
    ln_kernel<<<TOK, 256>>>(x, ln1g, ln1b, h);
    gemm_mma<3><<<dim3(8, 128), 256, SMEM2>>>(h, wr + OFF_WQ, nullptr, nullptr, q, DIM, DIM);
    gemm_mma<3><<<dim3(8, 128), 256, SMEM2>>>(h, wr + OFF_WK, nullptr, nullptr, k, DIM, DIM);
    gemm_mma<3><<<dim3(8, 128), 256, SMEM2>>>(h, wr + OFF_WV, nullptr, nullptr, v, DIM, DIM);
    qsm_kernel<<<(NBH*SEQ)/8, 256>>>(q, qh);
    ksm_partial<<<dim3(KCH, NBH), 256>>>(k, part);
    ksm_norm   <<<dim3(KCH, NBH), 256>>>(k, part);
    ctx_gemm   <<<dim3(4, 4, NBH), 256>>>(k, v, ctxh);
    gemm_mma<4><<<dim3(2, 32, NBH), 256, SMEM2>>>(qh, ctxh, nullptr, nullptr, attnh, DH, DH);
    gemm_mma<1><<<dim3(8, 128), 256, SMEM2>>>(attnh, wr + OFF_WO, bo, x, x1, DIM, DIM);

    // --- FFN block ---
    ln_kernel<<<TOK, 256>>>(x1, ln2g, ln2b, h);
    gemm_mma<2><<<dim3(32, 128), 256, SMEM2>>>(h, wr + OFF_WFF1, bff1, nullptr, ffh, FFD, DIM);
    gemm_mma<5><<<dim3(8, 128), 256, SMEM2>>>(ffh, wr + OFF_WFF2, bff2, x1, x2h, DIM, FFD);

    // --- trailing dense ---
    gemm_mma<0><<<dim3(8, 128), 256, SMEM2>>>(x2h, wr + OFF_WD, bd, nullptr, out, DIM, DIM);
}

// round 9
// speedup vs baseline: 3.4726x; 1.1762x over previous
#include <cuda_runtime.h>
#include <cuda_fp16.h>
#include <math.h>
#include <stdint.h>

#define BATCH 4
#define SEQ   4096
#define DIM   1024
#define NH    4
#define DH    256
#define FFD   4096
#define TOK   (BATCH*SEQ)   /* 16384 */
#define NBH   (BATCH*NH)    /* 16 */
#define KCH   16
#define CHUNK (SEQ/KCH)     /* 256 */

/* fp16 mma GEMM tiling: 128x128 CTA tile, 256 threads, 8 warps of 64x32 */
#define TM 128
#define TN 128
#define TK 64
#define APITCH 72
#define BPITCH 136
#define ABYTES (TM*APITCH*2)        /* 18432 */
#define BBYTES (TK*BPITCH*2)        /* 17408 */
#define SMEM2  (2*(ABYTES+BBYTES))  /* 71680 */

/* ctx mma tiling: 64x64 tiles, 128 threads, 4 warps of 32x32 */
#define CTK 64
#define CPITCH 72

// ---------------- scratch ---------------------------------------------------
__device__ float  g_q   [(size_t)NBH*SEQ*DH];
__device__ float  g_k   [(size_t)NBH*SEQ*DH];
__device__ float  g_x1  [(size_t)TOK*DIM];
__device__ float  g_part[NBH*KCH*2*DH];
__device__ __half g_h   [(size_t)TOK*DIM];
__device__ __half g_qh  [(size_t)NBH*SEQ*DH];
__device__ __half g_kh  [(size_t)NBH*SEQ*DH];
__device__ __half g_vh  [(size_t)NBH*SEQ*DH];
__device__ __half g_ctxh[(size_t)NBH*DH*DH];
__device__ __half g_attnh[(size_t)TOK*DIM];
__device__ __half g_ffh [(size_t)TOK*FFD];
__device__ __half g_x2h [(size_t)TOK*DIM];
__device__ __half g_wr  [(size_t)13*1024*1024];

/* offsets into g_wr (halves) */
#define OFF_WQ   (0)
#define OFF_WK   (1*1024*1024)
#define OFF_WV   (2*1024*1024)
#define OFF_WO   (3*1024*1024)
#define OFF_WD   (4*1024*1024)
#define OFF_WFF1 (5*1024*1024)
#define OFF_WFF2 (9*1024*1024)

__device__ __forceinline__ float gelu_tanh(float x) {
    float x3 = x*x*x;
    return 0.5f*x*(1.0f + tanhf(0.7978845608028654f*(x + 0.044715f*x3)));
}
__device__ __forceinline__ uint32_t smem_u32(const void* p) {
    uint32_t a;
    asm("{ .reg .u64 t; cvta.to.shared.u64 t, %1; cvt.u32.u64 %0, t; }" : "=r"(a) : "l"(p));
    return a;
}
__device__ __forceinline__ void cp16(uint32_t dst, const void* src) {
    asm volatile("cp.async.cg.shared.global [%0], [%1], 16;" :: "r"(dst), "l"(src));
}
__device__ __forceinline__ void ldm_x4(uint32_t* r, uint32_t addr) {
    asm volatile("ldmatrix.sync.aligned.m8n8.x4.shared.b16 {%0,%1,%2,%3}, [%4];"
        : "=r"(r[0]), "=r"(r[1]), "=r"(r[2]), "=r"(r[3]) : "r"(addr));
}
__device__ __forceinline__ void ldm_x4_t(uint32_t* r, uint32_t addr) {
    asm volatile("ldmatrix.sync.aligned.m8n8.x4.trans.shared.b16 {%0,%1,%2,%3}, [%4];"
        : "=r"(r[0]), "=r"(r[1]), "=r"(r[2]), "=r"(r[3]) : "r"(addr));
}
__device__ __forceinline__ void mma_f16(float* c, uint32_t a0, uint32_t a1, uint32_t a2,
                                        uint32_t a3, uint32_t b0, uint32_t b1) {
    asm volatile("mma.sync.aligned.m16n8k16.row.col.f32.f16.f16.f32 "
        "{%0,%1,%2,%3}, {%4,%5,%6,%7}, {%8,%9}, {%0,%1,%2,%3};"
        : "+f"(c[0]), "+f"(c[1]), "+f"(c[2]), "+f"(c[3])
        : "r"(a0), "r"(a1), "r"(a2), "r"(a3), "r"(b0), "r"(b1));
}

// ---------------- weight fp32 -> fp16 conversion -----------------------------
__global__ void cvt_kernel(const float* __restrict__ src, __half* __restrict__ dst, int n4)
{
    const int i = blockIdx.x * blockDim.x + threadIdx.x;
    if (i < n4) {
        float4 v = ((const float4*)src)[i];
        __half2* d2 = (__half2*)dst;
        d2[2*i]   = __floats2half2_rn(v.x, v.y);
        d2[2*i+1] = __floats2half2_rn(v.z, v.w);
    }
}

// ---------------- fp16 mma GEMM, 128x128 tiles, 256 threads ------------------
// MODE 0: C(fp32) = acc + bias
// MODE 1: C(fp32) = acc + bias + res
// MODE 2: C(fp16) = gelu(acc + bias)
// MODE 3: C(fp32) = acc scattered to [b,h,n,dh]
// MODE 4: batched attn out: A=qh+z*SEQ*DH, W=ctxh+z*DH*DH, C(fp16) scatter [b,n,d]
// MODE 5: C(fp16) = acc + bias + res
// MODE 6: C(fp16) = acc scattered to [b,h,n,dh]
template<int MODE>
__global__ void __launch_bounds__(256, 2)
gemm_mma(const __half* __restrict__ A, const __half* __restrict__ W,
         const float* __restrict__ bias, const float* __restrict__ res,
         void* __restrict__ Cv, int Ncols, int K)
{
    extern __shared__ char dsm[];
    const uint32_t aAs[2] = { smem_u32(dsm), smem_u32(dsm + ABYTES) };
    const uint32_t aBs[2] = { smem_u32(dsm + 2*ABYTES), smem_u32(dsm + 2*ABYTES + BBYTES) };

    if (MODE == 4) {
        A += (size_t)blockIdx.z * SEQ * DH;
        W += (size_t)blockIdx.z * DH * DH;
    }

    const int tid  = threadIdx.x;
    const int lane = tid & 31;
    const int w    = tid >> 5;
    const int m0w  = (w >> 2) * 64;
    const int n0w  = (w & 3) * 32;
    const int row0 = blockIdx.y * TM;
    const int col0 = blockIdx.x * TN;
    const int NT   = K / TK;

    const int lr = lane >> 2;
    const int lc = lane & 3;
    const int l15 = lane & 15;
    const int lhi8 = (lane >> 4) * 8;

    auto fill = [&](int buf, int k0) {
        #pragma unroll
        for (int j = 0; j < 4; j++) {
            int f  = tid + 256*j;
            int r  = f >> 3, c8 = f & 7;
            cp16(aAs[buf] + (uint32_t)(r*APITCH + c8*8)*2,
                 A + (size_t)(row0 + r)*K + k0 + c8*8);
        }
        #pragma unroll
        for (int j = 0; j < 4; j++) {
            int f  = tid + 256*j;
            int kr = f >> 4, c8 = f & 15;
            cp16(aBs[buf] + (uint32_t)(kr*BPITCH + c8*8)*2,
                 W + (size_t)(k0 + kr)*Ncols + col0 + c8*8);
        }
        asm volatile("cp.async.commit_group;");
    };

    float acc[4][4][4];
    #pragma unroll
    for (int i = 0; i < 4; i++)
        #pragma unroll
        for (int j = 0; j < 4; j++)
            #pragma unroll
            for (int r = 0; r < 4; r++) acc[i][j][r] = 0.f;

    fill(0, 0);

    for (int t = 0; t < NT; t++) {
        if (t + 1 < NT) {
            fill((t + 1) & 1, (t + 1) * TK);
            asm volatile("cp.async.wait_group 1;");
        } else {
            asm volatile("cp.async.wait_group 0;");
        }
        __syncthreads();

        const uint32_t a_lm = aAs[t & 1] + (uint32_t)((m0w + l15)*APITCH + lhi8)*2;
        const uint32_t b_lm = aBs[t & 1] + (uint32_t)(l15*BPITCH + n0w + lhi8)*2;

        #pragma unroll
        for (int kk = 0; kk < 4; kk++) {
            uint32_t af[4][4];
            #pragma unroll
            for (int mf = 0; mf < 4; mf++)
                ldm_x4(af[mf], a_lm + (uint32_t)(mf*16*APITCH + kk*16)*2);

            uint32_t bf[2][4];
            #pragma unroll
            for (int np = 0; np < 2; np++)
                ldm_x4_t(bf[np], b_lm + (uint32_t)(kk*16*BPITCH + np*16)*2);

            #pragma unroll
            for (int mf = 0; mf < 4; mf++)
                #pragma unroll
                for (int nf = 0; nf < 4; nf++)
                    mma_f16(acc[mf][nf],
                            af[mf][0], af[mf][1], af[mf][2], af[mf][3],
                            bf[nf >> 1][(nf & 1)*2], bf[nf >> 1][(nf & 1)*2 + 1]);
        }
        __syncthreads();
    }

    // ---- epilogue ----
    float*  Cf = (float*)Cv;
    __half* Ch = (__half*)Cv;
    #pragma unroll
    for (int mf = 0; mf < 4; mf++) {
        #pragma unroll
        for (int half_ = 0; half_ < 2; half_++) {
            const int grow = row0 + m0w + mf*16 + lr + half_*8;
            #pragma unroll
            for (int nf = 0; nf < 4; nf++) {
                const int gcol = col0 + n0w + nf*8 + 2*lc;
                float v0 = acc[mf][nf][half_*2 + 0];
                float v1 = acc[mf][nf][half_*2 + 1];
                if (MODE == 3 || MODE == 6) {
                    const int head = gcol >> 8;
                    const int dh0  = gcol & 255;
                    const int b_   = grow >> 12;
                    const int n_   = grow & 4095;
                    const size_t off = ((size_t)((b_*NH + head)*SEQ + n_))*DH + dh0;
                    if (MODE == 3) *(float2*)(Cf + off) = make_float2(v0, v1);
                    else           *(__half2*)(Ch + off) = __floats2half2_rn(v0, v1);
                } else if (MODE == 4) {
                    const int b_   = blockIdx.z >> 2;
                    const int head = blockIdx.z & 3;
                    __half2* op = (__half2*)(Ch + ((size_t)(b_*SEQ + grow))*DIM + head*DH + gcol);
                    *op = __floats2half2_rn(v0, v1);
                } else {
                    v0 += bias[gcol];
                    v1 += bias[gcol + 1];
                    if (MODE == 2) { v0 = gelu_tanh(v0); v1 = gelu_tanh(v1); }
                    if (MODE == 1 || MODE == 5) {
                        const float2 rv = *(const float2*)(res + (size_t)grow*Ncols + gcol);
                        v0 += rv.x; v1 += rv.y;
                    }
                    if (MODE == 2 || MODE == 5) {
                        *(__half2*)(Ch + (size_t)grow*Ncols + gcol) = __floats2half2_rn(v0, v1);
                    } else {
                        *(float2*)(Cf + (size_t)grow*Ncols + gcol) = make_float2(v0, v1);
                    }
                }
            }
        }
    }
}

// ---------------- ctx = k^T @ v (fp16 mma, both operands transposed) --------
__global__ void __launch_bounds__(128, 2)
ctx_mma(const __half* __restrict__ kh, const __half* __restrict__ vh,
        __half* __restrict__ ctx)
{
    __shared__ __half Ks[2][CTK][CPITCH];
    __shared__ __half Vs[2][CTK][CPITCH];
    const int bh = blockIdx.z;
    const int d0 = blockIdx.y * 64, e0 = blockIdx.x * 64;
    const __half* kb = kh + (size_t)bh*SEQ*DH;
    const __half* vb = vh + (size_t)bh*SEQ*DH;
    const int tid = threadIdx.x, lane = tid & 31, w = tid >> 5;
    const int m0w = (w >> 1) * 32, n0w = (w & 1) * 32;

    const uint32_t kbase[2] = { smem_u32(&Ks[0][0][0]), smem_u32(&Ks[1][0][0]) };
    const uint32_t vbase[2] = { smem_u32(&Vs[0][0][0]), smem_u32(&Vs[1][0][0]) };

    auto fill = [&](int buf, int n0) {
        #pragma unroll
        for (int j = 0; j < 4; j++) {
            int f = tid + 128*j;
            int r = f >> 3, c8 = f & 7;
            cp16(kbase[buf] + (uint32_t)(r*CPITCH + c8*8)*2, kb + (size_t)(n0+r)*DH + d0 + c8*8);
            cp16(vbase[buf] + (uint32_t)(r*CPITCH + c8*8)*2, vb + (size_t)(n0+r)*DH + e0 + c8*8);
        }
        asm volatile("cp.async.commit_group;");
    };

    float acc[2][4][4];
    #pragma unroll
    for (int i = 0; i < 2; i++)
        #pragma unroll
        for (int j = 0; j < 4; j++)
            #pragma unroll
            for (int r = 0; r < 4; r++) acc[i][j][r] = 0.f;

    /* A-trans lane mapping: matrices (m0-7/k0-7),(m8-15/k0-7),(m0-7/k8-15),(m8-15/k8-15) */
    const int arow = (lane & 7) + ((lane >> 4) << 3);   /* 0..15 k-row     */
    const int acol = ((lane >> 3) & 1) * 8;             /* 0 or 8 m-col    */
    const int l15 = lane & 15, lhi8 = (lane >> 4) * 8;
    const int lr = lane >> 2, lc = lane & 3;

    fill(0, 0);
    const int NTc = SEQ / CTK;   /* 64 */
    for (int t = 0; t < NTc; t++) {
        if (t + 1 < NTc) {
            fill((t + 1) & 1, (t + 1) * CTK);
            asm volatile("cp.async.wait_group 1;");
        } else {
            asm volatile("cp.async.wait_group 0;");
        }
        __syncthreads();
        const uint32_t ka = kbase[t & 1];
        const uint32_t va = vbase[t & 1];

        #pragma unroll
        for (int kk = 0; kk < 4; kk++) {
            uint32_t af[2][4];
            #pragma unroll
            for (int mf = 0; mf < 2; mf++)
                ldm_x4_t(af[mf], ka + (uint32_t)((kk*16 + arow)*CPITCH + m0w + mf*16 + acol)*2);
            uint32_t bf[2][4];
            #pragma unroll
            for (int np = 0; np < 2; np++)
                ldm_x4_t(bf[np], va + (uint32_t)((kk*16 + l15)*CPITCH + n0w + np*16 + lhi8)*2);
            #pragma unroll
            for (int mf = 0; mf < 2; mf++)
                #pragma unroll
                for (int nf = 0; nf < 4; nf++)
                    mma_f16(acc[mf][nf],
                            af[mf][0], af[mf][1], af[mf][2], af[mf][3],
                            bf[nf >> 1][(nf & 1)*2], bf[nf >> 1][(nf & 1)*2 + 1]);
        }
        __syncthreads();
    }

    __half* cb = ctx + (size_t)bh*DH*DH;
    #pragma unroll
    for (int mf = 0; mf < 2; mf++)
        #pragma unroll
        for (int half_ = 0; half_ < 2; half_++) {
            const int grow = d0 + m0w + mf*16 + lr + half_*8;
            #pragma unroll
            for (int nf = 0; nf < 4; nf++) {
                const int gcol = e0 + n0w + nf*8 + 2*lc;
                *(__half2*)(cb + (size_t)grow*DH + gcol) =
                    __floats2half2_rn(acc[mf][nf][half_*2], acc[mf][nf][half_*2 + 1]);
            }
        }
}

// ---------------- LayerNorm (fp32 in, fp16 out) ------------------------------
__global__ void ln_kernel(const float* __restrict__ x, const float* __restrict__ g,
                          const float* __restrict__ b, __half* __restrict__ out)
{
    __shared__ float red[16];
    __shared__ float s_mu, s_rstd;
    const int row = blockIdx.x, t = threadIdx.x;
    const float4 v = ((const float4*)(x + (size_t)row*DIM))[t];
    float s  = v.x + v.y + v.z + v.w;
    float ss = fmaf(v.x,v.x, fmaf(v.y,v.y, fmaf(v.z,v.z, v.w*v.w)));
    #pragma unroll
    for (int o = 16; o > 0; o >>= 1) {
        s  += __shfl_xor_sync(0xffffffffu, s,  o);
        ss += __shfl_xor_sync(0xffffffffu, ss, o);
    }
    const int w = t >> 5, lane = t & 31;
    if (lane == 0) { red[w] = s; red[8+w] = ss; }
    __syncthreads();
    if (t == 0) {
        float S = 0.f, SS = 0.f;
        #pragma unroll
        for (int i = 0; i < 8; i++) { S += red[i]; SS += red[8+i]; }
        float mu  = S  * (1.0f/DIM);
        float var = SS * (1.0f/DIM) - mu*mu;
        s_mu = mu; s_rstd = rsqrtf(var + 1e-5f);
    }
    __syncthreads();
    const float mu = s_mu, r = s_rstd;
    const float4 gv = ((const float4*)g)[t];
    const float4 bv = ((const float4*)b)[t];
    __half2* o2 = (__half2*)(out + (size_t)row*DIM);
    o2[t*2]   = __floats2half2_rn((v.x-mu)*r*gv.x + bv.x, (v.y-mu)*r*gv.y + bv.y);
    o2[t*2+1] = __floats2half2_rn((v.z-mu)*r*gv.z + bv.z, (v.w-mu)*r*gv.w + bv.w);
}

// ---------------- q softmax over head dim (fp32 in, fp16 out) ---------------
__global__ void qsm_kernel(const float* __restrict__ q, __half* __restrict__ qh)
{
    const int warp = (blockIdx.x * blockDim.x + threadIdx.x) >> 5;
    const int lane = threadIdx.x & 31;
    const float* row = q + (size_t)warp * DH;
    __half* rowh = qh + (size_t)warp * DH;
    float v[8];
    float m = -INFINITY;
    #pragma unroll
    for (int j = 0; j < 8; j++) { v[j] = row[j*32 + lane] * 0.25f; m = fmaxf(m, v[j]); }
    #pragma unroll
    for (int o = 16; o > 0; o >>= 1) m = fmaxf(m, __shfl_xor_sync(0xffffffffu, m, o));
    float s = 0.f;
    #pragma unroll
    for (int j = 0; j < 8; j++) { v[j] = expf(v[j] - m); s += v[j]; }
    #pragma unroll
    for (int o = 16; o > 0; o >>= 1) s += __shfl_xor_sync(0xffffffffu, s, o);
    const float inv = 1.0f / s;
    #pragma unroll
    for (int j = 0; j < 8; j++) rowh[j*32 + lane] = __float2half_rn(v[j] * inv);
}

// ---------------- k softmax over sequence dim (2-pass chunked) --------------
__global__ void ksm_partial(const float* __restrict__ k, float* __restrict__ part)
{
    const int bh = blockIdx.y, ch = blockIdx.x, t = threadIdx.x;
    const float* kp = k + ((size_t)bh*SEQ + (size_t)ch*CHUNK)*DH + t;
    float m = -INFINITY, s = 0.f;
    for (int i = 0; i < CHUNK; i++) {
        const float vv = kp[(size_t)i*DH] * 0.25f;
        const float nm = fmaxf(m, vv);
        s = s*expf(m - nm) + expf(vv - nm);
        m = nm;
    }
    float* pp = part + (size_t)((bh*KCH + ch)*2)*DH;
    pp[t] = m; pp[DH + t] = s;
}

__global__ void ksm_norm(const float* __restrict__ k, const float* __restrict__ part,
                         __half* __restrict__ kh)
{
    const int bh = blockIdx.y, ch = blockIdx.x, t = threadIdx.x;
    float M = -INFINITY;
    #pragma unroll
    for (int c = 0; c < KCH; c++)
        M = fmaxf(M, part[(size_t)((bh*KCH + c)*2)*DH + t]);
    float S = 0.f;
    #pragma unroll
    for (int c = 0; c < KCH; c++) {
        const float* pp = part + (size_t)((bh*KCH + c)*2)*DH;
        S += pp[DH + t] * expf(pp[t] - M);
    }
    const float inv = 1.0f / S;
    const float* kp = k + ((size_t)bh*SEQ + (size_t)ch*CHUNK)*DH + t;
    __half* khp = kh + ((size_t)bh*SEQ + (size_t)ch*CHUNK)*DH + t;
    for (int i = 0; i < CHUNK; i++) {
        const float vv = kp[(size_t)i*DH] * 0.25f;
        khp[(size_t)i*DH] = __float2half_rn(expf(vv - M) * inv);
    }
}

// ---------------- launch ----------------------------------------------------
extern "C" void kernel_launch(void* const* d_in, const int* in_sizes, int n_in,
                              void* d_out, int out_size)
{
    const float* x    = (const float*)d_in[0];
    const float* ln1g = (const float*)d_in[1];
    const float* ln1b = (const float*)d_in[2];
    const float* wq   = (const float*)d_in[3];
    const float* wk   = (const float*)d_in[4];
    const float* wv   = (const float*)d_in[5];
    const float* wo   = (const float*)d_in[6];
    const float* bo   = (const float*)d_in[7];
    const float* ln2g = (const float*)d_in[8];
    const float* ln2b = (const float*)d_in[9];
    const float* wff1 = (const float*)d_in[10];
    const float* bff1 = (const float*)d_in[11];
    const float* wff2 = (const float*)d_in[12];
    const float* bff2 = (const float*)d_in[13];
    const float* wd   = (const float*)d_in[14];
    const float* bd   = (const float*)d_in[15];
    float* out = (float*)d_out;

    float *q,*k,*x1,*part;
    __half *h,*qh,*kh,*vh,*ctxh,*attnh,*ffh,*x2h,*wr;
    cudaGetSymbolAddress((void**)&q,    g_q);
    cudaGetSymbolAddress((void**)&k,    g_k);
    cudaGetSymbolAddress((void**)&x1,   g_x1);
    cudaGetSymbolAddress((void**)&part, g_part);
    cudaGetSymbolAddress((void**)&h,    g_h);
    cudaGetSymbolAddress((void**)&qh,   g_qh);
    cudaGetSymbolAddress((void**)&kh,   g_kh);
    cudaGetSymbolAddress((void**)&vh,   g_vh);
    cudaGetSymbolAddress((void**)&ctxh, g_ctxh);
    cudaGetSymbolAddress((void**)&attnh,g_attnh);
    cudaGetSymbolAddress((void**)&ffh,  g_ffh);
    cudaGetSymbolAddress((void**)&x2h,  g_x2h);
    cudaGetSymbolAddress((void**)&wr,   g_wr);

    cudaFuncSetAttribute(gemm_mma<0>, cudaFuncAttributeMaxDynamicSharedMemorySize, SMEM2);
    cudaFuncSetAttribute(gemm_mma<1>, cudaFuncAttributeMaxDynamicSharedMemorySize, SMEM2);
    cudaFuncSetAttribute(gemm_mma<2>, cudaFuncAttributeMaxDynamicSharedMemorySize, SMEM2);
    cudaFuncSetAttribute(gemm_mma<3>, cudaFuncAttributeMaxDynamicSharedMemorySize, SMEM2);
    cudaFuncSetAttribute(gemm_mma<4>, cudaFuncAttributeMaxDynamicSharedMemorySize, SMEM2);
    cudaFuncSetAttribute(gemm_mma<5>, cudaFuncAttributeMaxDynamicSharedMemorySize, SMEM2);
    cudaFuncSetAttribute(gemm_mma<6>, cudaFuncAttributeMaxDynamicSharedMemorySize, SMEM2);

    // --- convert weights to fp16 ---
    const int n4_d  = DIM*DIM/4;
    const int n4_ff = DIM*FFD/4;
    cvt_kernel<<<n4_d/256, 256>>>(wq,   wr + OFF_WQ,   n4_d);
    cvt_kernel<<<n4_d/256, 256>>>(wk,   wr + OFF_WK,   n4_d);
    cvt_kernel<<<n4_d/256, 256>>>(wv,   wr + OFF_WV,   n4_d);
    cvt_kernel<<<n4_d/256, 256>>>(wo,   wr + OFF_WO,   n4_d);
    cvt_kernel<<<n4_d/256, 256>>>(wd,   wr + OFF_WD,   n4_d);
    cvt_kernel<<<n4_ff/256, 256>>>(wff1, wr + OFF_WFF1, n4_ff);
    cvt_kernel<<<n4_ff/256, 256>>>(wff2, wr + OFF_WFF2, n4_ff);

    // --- attention block ---
    ln_kernel<<<TOK, 256>>>(x, ln1g, ln1b, h);
    gemm_mma<3><<<dim3(8, 128), 256, SMEM2>>>(h, wr + OFF_WQ, nullptr, nullptr, q, DIM, DIM);
    gemm_mma<3><<<dim3(8, 128), 256, SMEM2>>>(h, wr + OFF_WK, nullptr, nullptr, k, DIM, DIM);
    gemm_mma<6><<<dim3(8, 128), 256, SMEM2>>>(h, wr + OFF_WV, nullptr, nullptr, vh, DIM, DIM);
    qsm_kernel<<<(NBH*SEQ)/8, 256>>>(q, qh);
    ksm_partial<<<dim3(KCH, NBH), 256>>>(k, part);
    ksm_norm   <<<dim3(KCH, NBH), 256>>>(k, part, kh);
    ctx_mma    <<<dim3(4, 4, NBH), 128>>>(kh, vh, ctxh);
    gemm_mma<4><<<dim3(2, 32, NBH), 256, SMEM2>>>(qh, ctxh, nullptr, nullptr, attnh, DH, DH);
    gemm_mma<1><<<dim3(8, 128), 256, SMEM2>>>(attnh, wr + OFF_WO, bo, x, x1, DIM, DIM);

    // --- FFN block ---
    ln_kernel<<<TOK, 256>>>(x1, ln2g, ln2b, h);
    gemm_mma<2><<<dim3(32, 128), 256, SMEM2>>>(h, wr + OFF_WFF1, bff1, nullptr, ffh, FFD, DIM);
    gemm_mma<5><<<dim3(8, 128), 256, SMEM2>>>(ffh, wr + OFF_WFF2, bff2, x1, x2h, DIM, FFD);

    // --- trailing dense ---
    gemm_mma<0><<<dim3(8, 128), 256, SMEM2>>>(x2h, wr + OFF_WD, bd, nullptr, out, DIM, DIM);
}

// round 10
// speedup vs baseline: 3.5034x; 1.0089x over previous
#include <cuda_runtime.h>
#include <cuda_fp16.h>
#include <math.h>
#include <stdint.h>

#define BATCH 4
#define SEQ   4096
#define DIM   1024
#define NH    4
#define DH    256
#define FFD   4096
#define TOK   (BATCH*SEQ)   /* 16384 */
#define NBH   (BATCH*NH)    /* 16 */
#define KCH   16
#define CHUNK (SEQ/KCH)     /* 256 */

/* fp16 mma GEMM tiling: 128x128 CTA tile, 256 threads, 8 warps of 64x32 */
#define TM 128
#define TN 128
#define TK 64
#define APITCH 72
#define BPITCH 136
#define ABYTES (TM*APITCH*2)        /* 18432 */
#define BBYTES (TK*BPITCH*2)        /* 17408 */
#define STAGEB (ABYTES+BBYTES)      /* 35840 */
#define SMEM3  (3*STAGEB)           /* 107520: 2 CTAs/SM = 210KB < 228KB */

/* ctx mma tiling: 64x64 tiles, 128 threads, 4 warps of 32x32 */
#define CTK 64
#define CPITCH 72

// ---------------- scratch ---------------------------------------------------
__device__ float  g_x1  [(size_t)TOK*DIM];
__device__ float  g_part[NBH*KCH*2*DH];
__device__ __half g_h   [(size_t)TOK*DIM];
__device__ __half g_qh  [(size_t)NBH*SEQ*DH];
__device__ __half g_kh  [(size_t)NBH*SEQ*DH];
__device__ __half g_vh  [(size_t)NBH*SEQ*DH];
__device__ __half g_ctxh[(size_t)NBH*DH*DH];
__device__ __half g_attnh[(size_t)TOK*DIM];
__device__ __half g_ffh [(size_t)TOK*FFD];
__device__ __half g_x2h [(size_t)TOK*DIM];
__device__ __half g_wr  [(size_t)13*1024*1024];

/* offsets into g_wr (halves) */
#define OFF_QKV  (0)                 /* packed [1024][3072]: wq|wk|wv */
#define OFF_WO   (3*1024*1024)
#define OFF_WD   (4*1024*1024)
#define OFF_WFF1 (5*1024*1024)
#define OFF_WFF2 (9*1024*1024)

__device__ __forceinline__ float gelu_tanh(float x) {
    float x3 = x*x*x;
    return 0.5f*x*(1.0f + tanhf(0.7978845608028654f*(x + 0.044715f*x3)));
}
__device__ __forceinline__ uint32_t smem_u32(const void* p) {
    uint32_t a;
    asm("{ .reg .u64 t; cvta.to.shared.u64 t, %1; cvt.u32.u64 %0, t; }" : "=r"(a) : "l"(p));
    return a;
}
__device__ __forceinline__ void cp16(uint32_t dst, const void* src) {
    asm volatile("cp.async.cg.shared.global [%0], [%1], 16;" :: "r"(dst), "l"(src));
}
__device__ __forceinline__ void ldm_x4(uint32_t* r, uint32_t addr) {
    asm volatile("ldmatrix.sync.aligned.m8n8.x4.shared.b16 {%0,%1,%2,%3}, [%4];"
        : "=r"(r[0]), "=r"(r[1]), "=r"(r[2]), "=r"(r[3]) : "r"(addr));
}
__device__ __forceinline__ void ldm_x4_t(uint32_t* r, uint32_t addr) {
    asm volatile("ldmatrix.sync.aligned.m8n8.x4.trans.shared.b16 {%0,%1,%2,%3}, [%4];"
        : "=r"(r[0]), "=r"(r[1]), "=r"(r[2]), "=r"(r[3]) : "r"(addr));
}
__device__ __forceinline__ void mma_f16(float* c, uint32_t a0, uint32_t a1, uint32_t a2,
                                        uint32_t a3, uint32_t b0, uint32_t b1) {
    asm volatile("mma.sync.aligned.m16n8k16.row.col.f32.f16.f16.f32 "
        "{%0,%1,%2,%3}, {%4,%5,%6,%7}, {%8,%9}, {%0,%1,%2,%3};"
        : "+f"(c[0]), "+f"(c[1]), "+f"(c[2]), "+f"(c[3])
        : "r"(a0), "r"(a1), "r"(a2), "r"(a3), "r"(b0), "r"(b1));
}

// ---------------- weight fp32 -> fp16 conversion -----------------------------
__global__ void cvt_kernel(const float* __restrict__ src, __half* __restrict__ dst, int n4)
{
    const int i = blockIdx.x * blockDim.x + threadIdx.x;
    if (i < n4) {
        float4 v = ((const float4*)src)[i];
        __half2* d2 = (__half2*)dst;
        d2[2*i]   = __floats2half2_rn(v.x, v.y);
        d2[2*i+1] = __floats2half2_rn(v.z, v.w);
    }
}

/* pack [1024][1024] fp32 into columns [base, base+1024) of [1024][3072] fp16 */
__global__ void cvt_qkv(const float* __restrict__ src, __half* __restrict__ dst, int base)
{
    const int i = blockIdx.x * blockDim.x + threadIdx.x;   /* 262144 float4 */
    const int row = i >> 8, c4 = i & 255;
    float4 v = ((const float4*)src)[i];
    __half2* d2 = (__half2*)(dst + (size_t)row*3072 + base + c4*4);
    d2[0] = __floats2half2_rn(v.x, v.y);
    d2[1] = __floats2half2_rn(v.z, v.w);
}

// ---------------- fp16 mma GEMM, 128x128 tiles, 3-stage pipeline -------------
// MODE 0: C(fp32) = acc + bias
// MODE 1: C(fp32) = acc + bias + res
// MODE 2: C(fp16) = gelu(acc + bias)
// MODE 4: batched attn out: A=qh+z*SEQ*DH, W=ctxh+z*DH*DH, C(fp16) scatter [b,n,d]
// MODE 5: C(fp16) = acc + bias + res
// MODE 7: fused qkv: W=[1024][3072], scatter fp16 to q/k/v [b,h,n,dh]
//         (q dst = Cv, k dst = bias cast, v dst = res cast)
template<int MODE>
__global__ void __launch_bounds__(256, 2)
gemm_mma(const __half* __restrict__ A, const __half* __restrict__ W,
         const float* __restrict__ bias, const float* __restrict__ res,
         void* __restrict__ Cv, int Ncols, int K)
{
    extern __shared__ char dsm[];
    uint32_t aAs[3], aBs[3];
    #pragma unroll
    for (int s = 0; s < 3; s++) {
        aAs[s] = smem_u32(dsm + s*STAGEB);
        aBs[s] = smem_u32(dsm + s*STAGEB + ABYTES);
    }

    if (MODE == 4) {
        A += (size_t)blockIdx.z * SEQ * DH;
        W += (size_t)blockIdx.z * DH * DH;
    }

    const int tid  = threadIdx.x;
    const int lane = tid & 31;
    const int w    = tid >> 5;
    const int m0w  = (w >> 2) * 64;
    const int n0w  = (w & 3) * 32;
    const int row0 = blockIdx.y * TM;
    const int col0 = blockIdx.x * TN;
    const int NT   = K / TK;

    const int lr = lane >> 2;
    const int lc = lane & 3;
    const int l15 = lane & 15;
    const int lhi8 = (lane >> 4) * 8;

    auto fill = [&](int buf, int k0) {
        #pragma unroll
        for (int j = 0; j < 4; j++) {
            int f  = tid + 256*j;
            int r  = f >> 3, c8 = f & 7;
            cp16(aAs[buf] + (uint32_t)(r*APITCH + c8*8)*2,
                 A + (size_t)(row0 + r)*K + k0 + c8*8);
        }
        #pragma unroll
        for (int j = 0; j < 4; j++) {
            int f  = tid + 256*j;
            int kr = f >> 4, c8 = f & 15;
            cp16(aBs[buf] + (uint32_t)(kr*BPITCH + c8*8)*2,
                 W + (size_t)(k0 + kr)*Ncols + col0 + c8*8);
        }
        asm volatile("cp.async.commit_group;");
    };

    float acc[4][4][4];
    #pragma unroll
    for (int i = 0; i < 4; i++)
        #pragma unroll
        for (int j = 0; j < 4; j++)
            #pragma unroll
            for (int r = 0; r < 4; r++) acc[i][j][r] = 0.f;

    fill(0, 0);
    fill(1, TK);

    int buf = 0;
    for (int t = 0; t < NT; t++) {
        if (t + 2 < NT) {
            fill((t + 2) % 3, (t + 2) * TK);
            asm volatile("cp.async.wait_group 2;");
        } else if (t + 1 < NT) {
            asm volatile("cp.async.wait_group 1;");
        } else {
            asm volatile("cp.async.wait_group 0;");
        }
        __syncthreads();

        const uint32_t a_lm = aAs[buf] + (uint32_t)((m0w + l15)*APITCH + lhi8)*2;
        const uint32_t b_lm = aBs[buf] + (uint32_t)(l15*BPITCH + n0w + lhi8)*2;

        #pragma unroll
        for (int kk = 0; kk < 4; kk++) {
            uint32_t af[4][4];
            #pragma unroll
            for (int mf = 0; mf < 4; mf++)
                ldm_x4(af[mf], a_lm + (uint32_t)(mf*16*APITCH + kk*16)*2);

            uint32_t bf[2][4];
            #pragma unroll
            for (int np = 0; np < 2; np++)
                ldm_x4_t(bf[np], b_lm + (uint32_t)(kk*16*BPITCH + np*16)*2);

            #pragma unroll
            for (int mf = 0; mf < 4; mf++)
                #pragma unroll
                for (int nf = 0; nf < 4; nf++)
                    mma_f16(acc[mf][nf],
                            af[mf][0], af[mf][1], af[mf][2], af[mf][3],
                            bf[nf >> 1][(nf & 1)*2], bf[nf >> 1][(nf & 1)*2 + 1]);
        }
        __syncthreads();
        buf = (buf + 1 == 3) ? 0 : buf + 1;
    }

    // ---- epilogue ----
    float*  Cf = (float*)Cv;
    __half* Ch = (__half*)Cv;
    #pragma unroll
    for (int mf = 0; mf < 4; mf++) {
        #pragma unroll
        for (int half_ = 0; half_ < 2; half_++) {
            const int grow = row0 + m0w + mf*16 + lr + half_*8;
            #pragma unroll
            for (int nf = 0; nf < 4; nf++) {
                const int gcol = col0 + n0w + nf*8 + 2*lc;
                float v0 = acc[mf][nf][half_*2 + 0];
                float v1 = acc[mf][nf][half_*2 + 1];
                if (MODE == 7) {
                    const int mat  = gcol >> 10;
                    const int hcol = gcol & 1023;
                    const int head = hcol >> 8;
                    const int dh0  = hcol & 255;
                    const int b_   = grow >> 12;
                    const int n_   = grow & 4095;
                    const size_t off = ((size_t)((b_*NH + head)*SEQ + n_))*DH + dh0;
                    __half* dst = (mat == 0) ? Ch : (mat == 1) ? (__half*)bias : (__half*)res;
                    *(__half2*)(dst + off) = __floats2half2_rn(v0, v1);
                } else if (MODE == 4) {
                    const int b_   = blockIdx.z >> 2;
                    const int head = blockIdx.z & 3;
                    __half2* op = (__half2*)(Ch + ((size_t)(b_*SEQ + grow))*DIM + head*DH + gcol);
                    *op = __floats2half2_rn(v0, v1);
                } else {
                    v0 += bias[gcol];
                    v1 += bias[gcol + 1];
                    if (MODE == 2) { v0 = gelu_tanh(v0); v1 = gelu_tanh(v1); }
                    if (MODE == 1 || MODE == 5) {
                        const float2 rv = *(const float2*)(res + (size_t)grow*Ncols + gcol);
                        v0 += rv.x; v1 += rv.y;
                    }
                    if (MODE == 2 || MODE == 5) {
                        *(__half2*)(Ch + (size_t)grow*Ncols + gcol) = __floats2half2_rn(v0, v1);
                    } else {
                        *(float2*)(Cf + (size_t)grow*Ncols + gcol) = make_float2(v0, v1);
                    }
                }
            }
        }
    }
}

// ---------------- ctx = k^T @ v (fp16 mma, both operands transposed) --------
__global__ void __launch_bounds__(128, 2)
ctx_mma(const __half* __restrict__ kh, const __half* __restrict__ vh,
        __half* __restrict__ ctx)
{
    __shared__ __half Ks[2][CTK][CPITCH];
    __shared__ __half Vs[2][CTK][CPITCH];
    const int bh = blockIdx.z;
    const int d0 = blockIdx.y * 64, e0 = blockIdx.x * 64;
    const __half* kb = kh + (size_t)bh*SEQ*DH;
    const __half* vb = vh + (size_t)bh*SEQ*DH;
    const int tid = threadIdx.x, lane = tid & 31, w = tid >> 5;
    const int m0w = (w >> 1) * 32, n0w = (w & 1) * 32;

    const uint32_t kbase[2] = { smem_u32(&Ks[0][0][0]), smem_u32(&Ks[1][0][0]) };
    const uint32_t vbase[2] = { smem_u32(&Vs[0][0][0]), smem_u32(&Vs[1][0][0]) };

    auto fill = [&](int buf, int n0) {
        #pragma unroll
        for (int j = 0; j < 4; j++) {
            int f = tid + 128*j;
            int r = f >> 3, c8 = f & 7;
            cp16(kbase[buf] + (uint32_t)(r*CPITCH + c8*8)*2, kb + (size_t)(n0+r)*DH + d0 + c8*8);
            cp16(vbase[buf] + (uint32_t)(r*CPITCH + c8*8)*2, vb + (size_t)(n0+r)*DH + e0 + c8*8);
        }
        asm volatile("cp.async.commit_group;");
    };

    float acc[2][4][4];
    #pragma unroll
    for (int i = 0; i < 2; i++)
        #pragma unroll
        for (int j = 0; j < 4; j++)
            #pragma unroll
            for (int r = 0; r < 4; r++) acc[i][j][r] = 0.f;

    const int arow = (lane & 7) + ((lane >> 4) << 3);
    const int acol = ((lane >> 3) & 1) * 8;
    const int l15 = lane & 15, lhi8 = (lane >> 4) * 8;
    const int lr = lane >> 2, lc = lane & 3;

    fill(0, 0);
    const int NTc = SEQ / CTK;
    for (int t = 0; t < NTc; t++) {
        if (t + 1 < NTc) {
            fill((t + 1) & 1, (t + 1) * CTK);
            asm volatile("cp.async.wait_group 1;");
        } else {
            asm volatile("cp.async.wait_group 0;");
        }
        __syncthreads();
        const uint32_t ka = kbase[t & 1];
        const uint32_t va = vbase[t & 1];

        #pragma unroll
        for (int kk = 0; kk < 4; kk++) {
            uint32_t af[2][4];
            #pragma unroll
            for (int mf = 0; mf < 2; mf++)
                ldm_x4_t(af[mf], ka + (uint32_t)((kk*16 + arow)*CPITCH + m0w + mf*16 + acol)*2);
            uint32_t bf[2][4];
            #pragma unroll
            for (int np = 0; np < 2; np++)
                ldm_x4_t(bf[np], va + (uint32_t)((kk*16 + l15)*CPITCH + n0w + np*16 + lhi8)*2);
            #pragma unroll
            for (int mf = 0; mf < 2; mf++)
                #pragma unroll
                for (int nf = 0; nf < 4; nf++)
                    mma_f16(acc[mf][nf],
                            af[mf][0], af[mf][1], af[mf][2], af[mf][3],
                            bf[nf >> 1][(nf & 1)*2], bf[nf >> 1][(nf & 1)*2 + 1]);
        }
        __syncthreads();
    }

    __half* cb = ctx + (size_t)bh*DH*DH;
    #pragma unroll
    for (int mf = 0; mf < 2; mf++)
        #pragma unroll
        for (int half_ = 0; half_ < 2; half_++) {
            const int grow = d0 + m0w + mf*16 + lr + half_*8;
            #pragma unroll
            for (int nf = 0; nf < 4; nf++) {
                const int gcol = e0 + n0w + nf*8 + 2*lc;
                *(__half2*)(cb + (size_t)grow*DH + gcol) =
                    __floats2half2_rn(acc[mf][nf][half_*2], acc[mf][nf][half_*2 + 1]);
            }
        }
}

// ---------------- LayerNorm (fp32 in, fp16 out) ------------------------------
__global__ void ln_kernel(const float* __restrict__ x, const float* __restrict__ g,
                          const float* __restrict__ b, __half* __restrict__ out)
{
    __shared__ float red[16];
    __shared__ float s_mu, s_rstd;
    const int row = blockIdx.x, t = threadIdx.x;
    const float4 v = ((const float4*)(x + (size_t)row*DIM))[t];
    float s  = v.x + v.y + v.z + v.w;
    float ss = fmaf(v.x,v.x, fmaf(v.y,v.y, fmaf(v.z,v.z, v.w*v.w)));
    #pragma unroll
    for (int o = 16; o > 0; o >>= 1) {
        s  += __shfl_xor_sync(0xffffffffu, s,  o);
        ss += __shfl_xor_sync(0xffffffffu, ss, o);
    }
    const int w = t >> 5, lane = t & 31;
    if (lane == 0) { red[w] = s; red[8+w] = ss; }
    __syncthreads();
    if (t == 0) {
        float S = 0.f, SS = 0.f;
        #pragma unroll
        for (int i = 0; i < 8; i++) { S += red[i]; SS += red[8+i]; }
        float mu  = S  * (1.0f/DIM);
        float var = SS * (1.0f/DIM) - mu*mu;
        s_mu = mu; s_rstd = rsqrtf(var + 1e-5f);
    }
    __syncthreads();
    const float mu = s_mu, r = s_rstd;
    const float4 gv = ((const float4*)g)[t];
    const float4 bv = ((const float4*)b)[t];
    __half2* o2 = (__half2*)(out + (size_t)row*DIM);
    o2[t*2]   = __floats2half2_rn((v.x-mu)*r*gv.x + bv.x, (v.y-mu)*r*gv.y + bv.y);
    o2[t*2+1] = __floats2half2_rn((v.z-mu)*r*gv.z + bv.z, (v.w-mu)*r*gv.w + bv.w);
}

// ---------------- q softmax over head dim (fp16 in-place) -------------------
__global__ void qsm_kernel(__half* __restrict__ q)
{
    const int warp = (blockIdx.x * blockDim.x + threadIdx.x) >> 5;
    const int lane = threadIdx.x & 31;
    __half* row = q + (size_t)warp * DH;
    float v[8];
    float m = -INFINITY;
    #pragma unroll
    for (int j = 0; j < 8; j++) {
        v[j] = __half2float(row[j*32 + lane]) * 0.25f;
        m = fmaxf(m, v[j]);
    }
    #pragma unroll
    for (int o = 16; o > 0; o >>= 1) m = fmaxf(m, __shfl_xor_sync(0xffffffffu, m, o));
    float s = 0.f;
    #pragma unroll
    for (int j = 0; j < 8; j++) { v[j] = expf(v[j] - m); s += v[j]; }
    #pragma unroll
    for (int o = 16; o > 0; o >>= 1) s += __shfl_xor_sync(0xffffffffu, s, o);
    const float inv = 1.0f / s;
    #pragma unroll
    for (int j = 0; j < 8; j++) row[j*32 + lane] = __float2half_rn(v[j] * inv);
}

// ---------------- k softmax over sequence dim (2-pass, fp16 in-place) -------
__global__ void ksm_partial(const __half* __restrict__ k, float* __restrict__ part)
{
    const int bh = blockIdx.y, ch = blockIdx.x, t = threadIdx.x;
    const __half* kp = k + ((size_t)bh*SEQ + (size_t)ch*CHUNK)*DH + t;
    float m = -INFINITY, s = 0.f;
    for (int i = 0; i < CHUNK; i++) {
        const float vv = __half2float(kp[(size_t)i*DH]) * 0.25f;
        const float nm = fmaxf(m, vv);
        s = s*expf(m - nm) + expf(vv - nm);
        m = nm;
    }
    float* pp = part + (size_t)((bh*KCH + ch)*2)*DH;
    pp[t] = m; pp[DH + t] = s;
}

__global__ void ksm_norm(__half* __restrict__ k, const float* __restrict__ part)
{
    const int bh = blockIdx.y, ch = blockIdx.x, t = threadIdx.x;
    float M = -INFINITY;
    #pragma unroll
    for (int c = 0; c < KCH; c++)
        M = fmaxf(M, part[(size_t)((bh*KCH + c)*2)*DH + t]);
    float S = 0.f;
    #pragma unroll
    for (int c = 0; c < KCH; c++) {
        const float* pp = part + (size_t)((bh*KCH + c)*2)*DH;
        S += pp[DH + t] * expf(pp[t] - M);
    }
    const float inv = 1.0f / S;
    __half* kp = k + ((size_t)bh*SEQ + (size_t)ch*CHUNK)*DH + t;
    for (int i = 0; i < CHUNK; i++) {
        const float vv = __half2float(kp[(size_t)i*DH]) * 0.25f;
        kp[(size_t)i*DH] = __float2half_rn(expf(vv - M) * inv);
    }
}

// ---------------- launch ----------------------------------------------------
extern "C" void kernel_launch(void* const* d_in, const int* in_sizes, int n_in,
                              void* d_out, int out_size)
{
    const float* x    = (const float*)d_in[0];
    const float* ln1g = (const float*)d_in[1];
    const float* ln1b = (const float*)d_in[2];
    const float* wq   = (const float*)d_in[3];
    const float* wk   = (const float*)d_in[4];
    const float* wv   = (const float*)d_in[5];
    const float* wo   = (const float*)d_in[6];
    const float* bo   = (const float*)d_in[7];
    const float* ln2g = (const float*)d_in[8];
    const float* ln2b = (const float*)d_in[9];
    const float* wff1 = (const float*)d_in[10];
    const float* bff1 = (const float*)d_in[11];
    const float* wff2 = (const float*)d_in[12];
    const float* bff2 = (const float*)d_in[13];
    const float* wd   = (const float*)d_in[14];
    const float* bd   = (const float*)d_in[15];
    float* out = (float*)d_out;

    float *x1,*part;
    __half *h,*qh,*kh,*vh,*ctxh,*attnh,*ffh,*x2h,*wr;
    cudaGetSymbolAddress((void**)&x1,   g_x1);
    cudaGetSymbolAddress((void**)&part, g_part);
    cudaGetSymbolAddress((void**)&h,    g_h);
    cudaGetSymbolAddress((void**)&qh,   g_qh);
    cudaGetSymbolAddress((void**)&kh,   g_kh);
    cudaGetSymbolAddress((void**)&vh,   g_vh);
    cudaGetSymbolAddress((void**)&ctxh, g_ctxh);
    cudaGetSymbolAddress((void**)&attnh,g_attnh);
    cudaGetSymbolAddress((void**)&ffh,  g_ffh);
    cudaGetSymbolAddress((void**)&x2h,  g_x2h);
    cudaGetSymbolAddress((void**)&wr,   g_wr);

    cudaFuncSetAttribute(gemm_mma<0>, cudaFuncAttributeMaxDynamicSharedMemorySize, SMEM3);
    cudaFuncSetAttribute(gemm_mma<1>, cudaFuncAttributeMaxDynamicSharedMemorySize, SMEM3);
    cudaFuncSetAttribute(gemm_mma<2>, cudaFuncAttributeMaxDynamicSharedMemorySize, SMEM3);
    cudaFuncSetAttribute(gemm_mma<4>, cudaFuncAttributeMaxDynamicSharedMemorySize, SMEM3);
    cudaFuncSetAttribute(gemm_mma<5>, cudaFuncAttributeMaxDynamicSharedMemorySize, SMEM3);
    cudaFuncSetAttribute(gemm_mma<7>, cudaFuncAttributeMaxDynamicSharedMemorySize, SMEM3);

    // --- convert weights to fp16 (qkv packed into [1024][3072]) ---
    const int n4_d  = DIM*DIM/4;
    const int n4_ff = DIM*FFD/4;
    cvt_qkv<<<n4_d/256, 256>>>(wq, wr + OFF_QKV, 0);
    cvt_qkv<<<n4_d/256, 256>>>(wk, wr + OFF_QKV, 1024);
    cvt_qkv<<<n4_d/256, 256>>>(wv, wr + OFF_QKV, 2048);
    cvt_kernel<<<n4_d/256, 256>>>(wo,   wr + OFF_WO,   n4_d);
    cvt_kernel<<<n4_d/256, 256>>>(wd,   wr + OFF_WD,   n4_d);
    cvt_kernel<<<n4_ff/256, 256>>>(wff1, wr + OFF_WFF1, n4_ff);
    cvt_kernel<<<n4_ff/256, 256>>>(wff2, wr + OFF_WFF2, n4_ff);

    // --- attention block ---
    ln_kernel<<<TOK, 256>>>(x, ln1g, ln1b, h);
    gemm_mma<7><<<dim3(24, 128), 256, SMEM3>>>(h, wr + OFF_QKV,
                                               (const float*)kh, (const float*)vh,
                                               qh, 3*DIM, DIM);
    qsm_kernel<<<(NBH*SEQ)/8, 256>>>(qh);
    ksm_partial<<<dim3(KCH, NBH), 256>>>(kh, part);
    ksm_norm   <<<dim3(KCH, NBH), 256>>>(kh, part);
    ctx_mma    <<<dim3(4, 4, NBH), 128>>>(kh, vh, ctxh);
    gemm_mma<4><<<dim3(2, 32, NBH), 256, SMEM3>>>(qh, ctxh, nullptr, nullptr, attnh, DH, DH);
    gemm_mma<1><<<dim3(8, 128), 256, SMEM3>>>(attnh, wr + OFF_WO, bo, x, x1, DIM, DIM);

    // --- FFN block ---
    ln_kernel<<<TOK, 256>>>(x1, ln2g, ln2b, h);
    gemm_mma<2><<<dim3(32, 128), 256, SMEM3>>>(h, wr + OFF_WFF1, bff1, nullptr, ffh, FFD, DIM);
    gemm_mma<5><<<dim3(8, 128), 256, SMEM3>>>(ffh, wr + OFF_WFF2, bff2, x1, x2h, DIM, FFD);

    // --- trailing dense ---
    gemm_mma<0><<<dim3(8, 128), 256, SMEM3>>>(x2h, wr + OFF_WD, bd, nullptr, out, DIM, DIM);
}

// round 12
// speedup vs baseline: 3.5610x; 1.0164x over previous
#include <cuda_runtime.h>
#include <cuda_fp16.h>
#include <math.h>
#include <stdint.h>

#define BATCH 4
#define SEQ   4096
#define DIM   1024
#define NH    4
#define DH    256
#define FFD   4096
#define TOK   (BATCH*SEQ)   /* 16384 */
#define NBH   (BATCH*NH)    /* 16 */
#define KCH   16
#define CHUNK (SEQ/KCH)     /* 256 */

/* fp16 mma GEMM tiling: 128x128 CTA tile, 256 threads, 8 warps of 64x32 */
#define TM 128
#define TN 128
#define TK 64
#define APITCH 72
#define BPITCH 136
#define ABYTES (TM*APITCH*2)        /* 18432 */
#define BBYTES (TK*BPITCH*2)        /* 17408 */
#define STAGEB (ABYTES+BBYTES)      /* 35840 */
#define SMEM3  (3*STAGEB)           /* 107520: 2 CTAs/SM = 210KB < 228KB */

/* ctx mma tiling: 64x64 tiles, 128 threads, 4 warps of 32x32 */
#define CTK 64
#define CPITCH 72

// ---------------- scratch ---------------------------------------------------
__device__ float  g_x1  [(size_t)TOK*DIM];
__device__ float  g_part[NBH*KCH*2*DH];
__device__ __half g_h   [(size_t)TOK*DIM];
__device__ __half g_qh  [(size_t)TOK*DIM];      /* q token-major [b,n,h,dh] */
__device__ __half g_kh  [(size_t)NBH*SEQ*DH];
__device__ __half g_vh  [(size_t)NBH*SEQ*DH];
__device__ __half g_ctxh[(size_t)NBH*DH*DH];
__device__ __half g_w2h [(size_t)BATCH*DIM*DIM]; /* W2_b = blockdiag(ctx_{b,h}) @ wo */
__device__ __half g_ffh [(size_t)TOK*FFD];
__device__ __half g_x2h [(size_t)TOK*DIM];
__device__ __half g_wr  [(size_t)13*1024*1024];

/* offsets into g_wr (halves) */
#define OFF_QKV  (0)                 /* packed [1024][3072]: wq|wk|wv */
#define OFF_WO   (3*1024*1024)
#define OFF_WD   (4*1024*1024)
#define OFF_WFF1 (5*1024*1024)
#define OFF_WFF2 (9*1024*1024)

__device__ __forceinline__ float gelu_tanh(float x) {
    float x3 = x*x*x;
    return 0.5f*x*(1.0f + tanhf(0.7978845608028654f*(x + 0.044715f*x3)));
}
__device__ __forceinline__ uint32_t smem_u32(const void* p) {
    uint32_t a;
    asm("{ .reg .u64 t; cvta.to.shared.u64 t, %1; cvt.u32.u64 %0, t; }" : "=r"(a) : "l"(p));
    return a;
}
__device__ __forceinline__ void cp16(uint32_t dst, const void* src) {
    asm volatile("cp.async.cg.shared.global [%0], [%1], 16;" :: "r"(dst), "l"(src));
}
__device__ __forceinline__ void ldm_x4(uint32_t* r, uint32_t addr) {
    asm volatile("ldmatrix.sync.aligned.m8n8.x4.shared.b16 {%0,%1,%2,%3}, [%4];"
        : "=r"(r[0]), "=r"(r[1]), "=r"(r[2]), "=r"(r[3]) : "r"(addr));
}
__device__ __forceinline__ void ldm_x4_t(uint32_t* r, uint32_t addr) {
    asm volatile("ldmatrix.sync.aligned.m8n8.x4.trans.shared.b16 {%0,%1,%2,%3}, [%4];"
        : "=r"(r[0]), "=r"(r[1]), "=r"(r[2]), "=r"(r[3]) : "r"(addr));
}
__device__ __forceinline__ void mma_f16(float* c, uint32_t a0, uint32_t a1, uint32_t a2,
                                        uint32_t a3, uint32_t b0, uint32_t b1) {
    asm volatile("mma.sync.aligned.m16n8k16.row.col.f32.f16.f16.f32 "
        "{%0,%1,%2,%3}, {%4,%5,%6,%7}, {%8,%9}, {%0,%1,%2,%3};"
        : "+f"(c[0]), "+f"(c[1]), "+f"(c[2]), "+f"(c[3])
        : "r"(a0), "r"(a1), "r"(a2), "r"(a3), "r"(b0), "r"(b1));
}

// ---------------- weight fp32 -> fp16 conversion -----------------------------
__global__ void cvt_kernel(const float* __restrict__ src, __half* __restrict__ dst, int n4)
{
    const int i = blockIdx.x * blockDim.x + threadIdx.x;
    if (i < n4) {
        float4 v = ((const float4*)src)[i];
        __half2* d2 = (__half2*)dst;
        d2[2*i]   = __floats2half2_rn(v.x, v.y);
        d2[2*i+1] = __floats2half2_rn(v.z, v.w);
    }
}

/* pack [1024][1024] fp32 into columns [base, base+1024) of [1024][3072] fp16 */
__global__ void cvt_qkv(const float* __restrict__ src, __half* __restrict__ dst, int base)
{
    const int i = blockIdx.x * blockDim.x + threadIdx.x;
    const int row = i >> 8, c4 = i & 255;
    float4 v = ((const float4*)src)[i];
    __half2* d2 = (__half2*)(dst + (size_t)row*3072 + base + c4*4);
    d2[0] = __floats2half2_rn(v.x, v.y);
    d2[1] = __floats2half2_rn(v.z, v.w);
}

// ---------------- fp16 mma GEMM, 128x128 tiles, 3-stage, 1 bar/iter ----------
// MODE 0: C(fp32) = acc + bias
// MODE 1: C(fp32) = acc + bias + res
// MODE 2: C(fp16) = gelu(acc + bias)
// MODE 5: C(fp16) = acc + bias + res
// MODE 7: fused qkv: W=[1024][3072]; q -> Cv row-major [TOK][1024];
//         k -> bias cast scatter [b,h,n,dh]; v -> res cast scatter
// MODE 8: W2 batch z=bh: A=ctx+z*DH*DH (K=256, 256 rows), W=wo+(z&3)*DH*Ncols,
//         C(fp16) at w2 + (z>>2)*DIM*Ncols + (z&3)*DH*Ncols
// MODE 9: batched MODE 1 over z=b: A=qh+z*SEQ*K, W=w2+z*K*Ncols,
//         res/C offset z*SEQ*Ncols
template<int MODE>
__global__ void __launch_bounds__(256, 2)
gemm_mma(const __half* __restrict__ A, const __half* __restrict__ W,
         const float* __restrict__ bias, const float* __restrict__ res,
         void* __restrict__ Cv, int Ncols, int K)
{
    extern __shared__ char dsm[];
    uint32_t aAs[3], aBs[3];
    #pragma unroll
    for (int s = 0; s < 3; s++) {
        aAs[s] = smem_u32(dsm + s*STAGEB);
        aBs[s] = smem_u32(dsm + s*STAGEB + ABYTES);
    }

    size_t cofs = 0;
    if (MODE == 8) {
        const int z = blockIdx.z;
        A += (size_t)z * DH * DH;
        W += (size_t)(z & 3) * DH * Ncols;
        cofs = (size_t)(z >> 2) * DIM * Ncols + (size_t)(z & 3) * DH * Ncols;
    }
    if (MODE == 9) {
        const int z = blockIdx.z;
        A += (size_t)z * SEQ * K;
        W += (size_t)z * K * Ncols;
        res += (size_t)z * SEQ * Ncols;
        cofs = (size_t)z * SEQ * Ncols;
    }

    const int tid  = threadIdx.x;
    const int lane = tid & 31;
    const int w    = tid >> 5;
    const int m0w  = (w >> 2) * 64;
    const int n0w  = (w & 3) * 32;
    const int row0 = blockIdx.y * TM;
    const int col0 = blockIdx.x * TN;
    const int NT   = K / TK;

    const int lr = lane >> 2;
    const int lc = lane & 3;
    const int l15 = lane & 15;
    const int lhi8 = (lane >> 4) * 8;

    auto fill = [&](int buf, int k0) {
        #pragma unroll
        for (int j = 0; j < 4; j++) {
            int f  = tid + 256*j;
            int r  = f >> 3, c8 = f & 7;
            cp16(aAs[buf] + (uint32_t)(r*APITCH + c8*8)*2,
                 A + (size_t)(row0 + r)*K + k0 + c8*8);
        }
        #pragma unroll
        for (int j = 0; j < 4; j++) {
            int f  = tid + 256*j;
            int kr = f >> 4, c8 = f & 15;
            cp16(aBs[buf] + (uint32_t)(kr*BPITCH + c8*8)*2,
                 W + (size_t)(k0 + kr)*Ncols + col0 + c8*8);
        }
        asm volatile("cp.async.commit_group;");
    };

    float acc[4][4][4];
    #pragma unroll
    for (int i = 0; i < 4; i++)
        #pragma unroll
        for (int j = 0; j < 4; j++)
            #pragma unroll
            for (int r = 0; r < 4; r++) acc[i][j][r] = 0.f;

    fill(0, 0);
    fill(1, TK);

    int buf = 0;
    for (int t = 0; t < NT; t++) {
        if (t + 1 < NT) asm volatile("cp.async.wait_group 1;");
        else            asm volatile("cp.async.wait_group 0;");
        __syncthreads();
        if (t + 2 < NT) fill((t + 2) % 3, (t + 2) * TK);

        const uint32_t a_lm = aAs[buf] + (uint32_t)((m0w + l15)*APITCH + lhi8)*2;
        const uint32_t b_lm = aBs[buf] + (uint32_t)(l15*BPITCH + n0w + lhi8)*2;

        #pragma unroll
        for (int kk = 0; kk < 4; kk++) {
            uint32_t af[4][4];
            #pragma unroll
            for (int mf = 0; mf < 4; mf++)
                ldm_x4(af[mf], a_lm + (uint32_t)(mf*16*APITCH + kk*16)*2);

            uint32_t bf[2][4];
            #pragma unroll
            for (int np = 0; np < 2; np++)
                ldm_x4_t(bf[np], b_lm + (uint32_t)(kk*16*BPITCH + np*16)*2);

            #pragma unroll
            for (int mf = 0; mf < 4; mf++)
                #pragma unroll
                for (int nf = 0; nf < 4; nf++)
                    mma_f16(acc[mf][nf],
                            af[mf][0], af[mf][1], af[mf][2], af[mf][3],
                            bf[nf >> 1][(nf & 1)*2], bf[nf >> 1][(nf & 1)*2 + 1]);
        }
        buf = (buf + 1 == 3) ? 0 : buf + 1;
    }

    // ---- epilogue ----
    float*  Cf = (float*)Cv;
    __half* Ch = (__half*)Cv;
    #pragma unroll
    for (int mf = 0; mf < 4; mf++) {
        #pragma unroll
        for (int half_ = 0; half_ < 2; half_++) {
            const int grow = row0 + m0w + mf*16 + lr + half_*8;
            #pragma unroll
            for (int nf = 0; nf < 4; nf++) {
                const int gcol = col0 + n0w + nf*8 + 2*lc;
                float v0 = acc[mf][nf][half_*2 + 0];
                float v1 = acc[mf][nf][half_*2 + 1];
                if (MODE == 7) {
                    const int mat  = gcol >> 10;
                    const int hcol = gcol & 1023;
                    if (mat == 0) {
                        *(__half2*)(Ch + (size_t)grow*DIM + hcol) = __floats2half2_rn(v0, v1);
                    } else {
                        const int head = hcol >> 8;
                        const int dh0  = hcol & 255;
                        const int b_   = grow >> 12;
                        const int n_   = grow & 4095;
                        const size_t off = ((size_t)((b_*NH + head)*SEQ + n_))*DH + dh0;
                        __half* dst = (mat == 1) ? (__half*)bias : (__half*)res;
                        *(__half2*)(dst + off) = __floats2half2_rn(v0, v1);
                    }
                } else if (MODE == 8) {
                    *(__half2*)(Ch + cofs + (size_t)grow*Ncols + gcol) = __floats2half2_rn(v0, v1);
                } else {
                    v0 += bias[gcol];
                    v1 += bias[gcol + 1];
                    if (MODE == 2) { v0 = gelu_tanh(v0); v1 = gelu_tanh(v1); }
                    if (MODE == 1 || MODE == 5 || MODE == 9) {
                        const float2 rv = *(const float2*)(res + (size_t)grow*Ncols + gcol);
                        v0 += rv.x; v1 += rv.y;
                    }
                    if (MODE == 2 || MODE == 5) {
                        *(__half2*)(Ch + (size_t)grow*Ncols + gcol) = __floats2half2_rn(v0, v1);
                    } else {
                        *(float2*)(Cf + cofs + (size_t)grow*Ncols + gcol) = make_float2(v0, v1);
                    }
                }
            }
        }
    }
}

// ---------------- ctx = k^T @ v (fp16 mma, both operands transposed) --------
__global__ void __launch_bounds__(128, 2)
ctx_mma(const __half* __restrict__ kh, const __half* __restrict__ vh,
        __half* __restrict__ ctx)
{
    __shared__ __half Ks[2][CTK][CPITCH];
    __shared__ __half Vs[2][CTK][CPITCH];
    const int bh = blockIdx.z;
    const int d0 = blockIdx.y * 64, e0 = blockIdx.x * 64;
    const __half* kb = kh + (size_t)bh*SEQ*DH;
    const __half* vb = vh + (size_t)bh*SEQ*DH;
    const int tid = threadIdx.x, lane = tid & 31, w = tid >> 5;
    const int m0w = (w >> 1) * 32, n0w = (w & 1) * 32;

    const uint32_t kbase[2] = { smem_u32(&Ks[0][0][0]), smem_u32(&Ks[1][0][0]) };
    const uint32_t vbase[2] = { smem_u32(&Vs[0][0][0]), smem_u32(&Vs[1][0][0]) };

    auto fill = [&](int buf, int n0) {
        #pragma unroll
        for (int j = 0; j < 4; j++) {
            int f = tid + 128*j;
            int r = f >> 3, c8 = f & 7;
            cp16(kbase[buf] + (uint32_t)(r*CPITCH + c8*8)*2, kb + (size_t)(n0+r)*DH + d0 + c8*8);
            cp16(vbase[buf] + (uint32_t)(r*CPITCH + c8*8)*2, vb + (size_t)(n0+r)*DH + e0 + c8*8);
        }
        asm volatile("cp.async.commit_group;");
    };

    float acc[2][4][4];
    #pragma unroll
    for (int i = 0; i < 2; i++)
        #pragma unroll
        for (int j = 0; j < 4; j++)
            #pragma unroll
            for (int r = 0; r < 4; r++) acc[i][j][r] = 0.f;

    const int arow = (lane & 7) + ((lane >> 4) << 3);
    const int acol = ((lane >> 3) & 1) * 8;
    const int l15 = lane & 15, lhi8 = (lane >> 4) * 8;
    const int lr = lane >> 2, lc = lane & 3;

    fill(0, 0);
    const int NTc = SEQ / CTK;
    for (int t = 0; t < NTc; t++) {
        if (t + 1 < NTc) {
            fill((t + 1) & 1, (t + 1) * CTK);
            asm volatile("cp.async.wait_group 1;");
        } else {
            asm volatile("cp.async.wait_group 0;");
        }
        __syncthreads();
        const uint32_t ka = kbase[t & 1];
        const uint32_t va = vbase[t & 1];

        #pragma unroll
        for (int kk = 0; kk < 4; kk++) {
            uint32_t af[2][4];
            #pragma unroll
            for (int mf = 0; mf < 2; mf++)
                ldm_x4_t(af[mf], ka + (uint32_t)((kk*16 + arow)*CPITCH + m0w + mf*16 + acol)*2);
            uint32_t bf[2][4];
            #pragma unroll
            for (int np = 0; np < 2; np++)
                ldm_x4_t(bf[np], va + (uint32_t)((kk*16 + l15)*CPITCH + n0w + np*16 + lhi8)*2);
            #pragma unroll
            for (int mf = 0; mf < 2; mf++)
                #pragma unroll
                for (int nf = 0; nf < 4; nf++)
                    mma_f16(acc[mf][nf],
                            af[mf][0], af[mf][1], af[mf][2], af[mf][3],
                            bf[nf >> 1][(nf & 1)*2], bf[nf >> 1][(nf & 1)*2 + 1]);
        }
        __syncthreads();
    }

    __half* cb = ctx + (size_t)bh*DH*DH;
    #pragma unroll
    for (int mf = 0; mf < 2; mf++)
        #pragma unroll
        for (int half_ = 0; half_ < 2; half_++) {
            const int grow = d0 + m0w + mf*16 + lr + half_*8;
            #pragma unroll
            for (int nf = 0; nf < 4; nf++) {
                const int gcol = e0 + n0w + nf*8 + 2*lc;
                *(__half2*)(cb + (size_t)grow*DH + gcol) =
                    __floats2half2_rn(acc[mf][nf][half_*2], acc[mf][nf][half_*2 + 1]);
            }
        }
}

// ---------------- LayerNorm (fp32 in, fp16 out) ------------------------------
__global__ void ln_kernel(const float* __restrict__ x, const float* __restrict__ g,
                          const float* __restrict__ b, __half* __restrict__ out)
{
    __shared__ float red[16];
    __shared__ float s_mu, s_rstd;
    const int row = blockIdx.x, t = threadIdx.x;
    const float4 v = ((const float4*)(x + (size_t)row*DIM))[t];
    float s  = v.x + v.y + v.z + v.w;
    float ss = fmaf(v.x,v.x, fmaf(v.y,v.y, fmaf(v.z,v.z, v.w*v.w)));
    #pragma unroll
    for (int o = 16; o > 0; o >>= 1) {
        s  += __shfl_xor_sync(0xffffffffu, s,  o);
        ss += __shfl_xor_sync(0xffffffffu, ss, o);
    }
    const int w = t >> 5, lane = t & 31;
    if (lane == 0) { red[w] = s; red[8+w] = ss; }
    __syncthreads();
    if (t == 0) {
        float S = 0.f, SS = 0.f;
        #pragma unroll
        for (int i = 0; i < 8; i++) { S += red[i]; SS += red[8+i]; }
        float mu  = S  * (1.0f/DIM);
        float var = SS * (1.0f/DIM) - mu*mu;
        s_mu = mu; s_rstd = rsqrtf(var + 1e-5f);
    }
    __syncthreads();
    const float mu = s_mu, r = s_rstd;
    const float4 gv = ((const float4*)g)[t];
    const float4 bv = ((const float4*)b)[t];
    __half2* o2 = (__half2*)(out + (size_t)row*DIM);
    o2[t*2]   = __floats2half2_rn((v.x-mu)*r*gv.x + bv.x, (v.y-mu)*r*gv.y + bv.y);
    o2[t*2+1] = __floats2half2_rn((v.z-mu)*r*gv.z + bv.z, (v.w-mu)*r*gv.w + bv.w);
}

// ---------------- q softmax over head dim (fp16 in-place) -------------------
__global__ void qsm_kernel(__half* __restrict__ q)
{
    const int warp = (blockIdx.x * blockDim.x + threadIdx.x) >> 5;
    const int lane = threadIdx.x & 31;
    __half* row = q + (size_t)warp * DH;
    float v[8];
    float m = -INFINITY;
    #pragma unroll
    for (int j = 0; j < 8; j++) {
        v[j] = __half2float(row[j*32 + lane]) * 0.25f;
        m = fmaxf(m, v[j]);
    }
    #pragma unroll
    for (int o = 16; o > 0; o >>= 1) m = fmaxf(m, __shfl_xor_sync(0xffffffffu, m, o));
    float s = 0.f;
    #pragma unroll
    for (int j = 0; j < 8; j++) { v[j] = expf(v[j] - m); s += v[j]; }
    #pragma unroll
    for (int o = 16; o > 0; o >>= 1) s += __shfl_xor_sync(0xffffffffu, s, o);
    const float inv = 1.0f / s;
    #pragma unroll
    for (int j = 0; j < 8; j++) row[j*32 + lane] = __float2half_rn(v[j] * inv);
}

// ---------------- k softmax over sequence dim (2-pass, fp16 in-place) -------
__global__ void ksm_partial(const __half* __restrict__ k, float* __restrict__ part)
{
    const int bh = blockIdx.y, ch = blockIdx.x, t = threadIdx.x;
    const __half* kp = k + ((size_t)bh*SEQ + (size_t)ch*CHUNK)*DH + t;
    float m = -INFINITY, s = 0.f;
    for (int i = 0; i < CHUNK; i++) {
        const float vv = __half2float(kp[(size_t)i*DH]) * 0.25f;
        const float nm = fmaxf(m, vv);
        s = s*expf(m - nm) + expf(vv - nm);
        m = nm;
    }
    float* pp = part + (size_t)((bh*KCH + ch)*2)*DH;
    pp[t] = m; pp[DH + t] = s;
}

__global__ void ksm_norm(__half* __restrict__ k, const float* __restrict__ part)
{
    const int bh = blockIdx.y, ch = blockIdx.x, t = threadIdx.x;
    float M = -INFINITY;
    #pragma unroll
    for (int c = 0; c < KCH; c++)
        M = fmaxf(M, part[(size_t)((bh*KCH + c)*2)*DH + t]);
    float S = 0.f;
    #pragma unroll
    for (int c = 0; c < KCH; c++) {
        const float* pp = part + (size_t)((bh*KCH + c)*2)*DH;
        S += pp[DH + t] * expf(pp[t] - M);
    }
    const float inv = 1.0f / S;
    __half* kp = k + ((size_t)bh*SEQ + (size_t)ch*CHUNK)*DH + t;
    for (int i = 0; i < CHUNK; i++) {
        const float vv = __half2float(kp[(size_t)i*DH]) * 0.25f;
        kp[(size_t)i*DH] = __float2half_rn(expf(vv - M) * inv);
    }
}

// ---------------- launch ----------------------------------------------------
extern "C" void kernel_launch(void* const* d_in, const int* in_sizes, int n_in,
                              void* d_out, int out_size)
{
    const float* x    = (const float*)d_in[0];
    const float* ln1g = (const float*)d_in[1];
    const float* ln1b = (const float*)d_in[2];
    const float* wq   = (const float*)d_in[3];
    const float* wk   = (const float*)d_in[4];
    const float* wv   = (const float*)d_in[5];
    const float* wo   = (const float*)d_in[6];
    const float* bo   = (const float*)d_in[7];
    const float* ln2g = (const float*)d_in[8];
    const float* ln2b = (const float*)d_in[9];
    const float* wff1 = (const float*)d_in[10];
    const float* bff1 = (const float*)d_in[11];
    const float* wff2 = (const float*)d_in[12];
    const float* bff2 = (const float*)d_in[13];
    const float* wd   = (const float*)d_in[14];
    const float* bd   = (const float*)d_in[15];
    float* out = (float*)d_out;

    float *x1,*part;
    __half *h,*qh,*kh,*vh,*ctxh,*w2h,*ffh,*x2h,*wr;
    cudaGetSymbolAddress((void**)&x1,   g_x1);
    cudaGetSymbolAddress((void**)&part, g_part);
    cudaGetSymbolAddress((void**)&h,    g_h);
    cudaGetSymbolAddress((void**)&qh,   g_qh);
    cudaGetSymbolAddress((void**)&kh,   g_kh);
    cudaGetSymbolAddress((void**)&vh,   g_vh);
    cudaGetSymbolAddress((void**)&ctxh, g_ctxh);
    cudaGetSymbolAddress((void**)&w2h,  g_w2h);
    cudaGetSymbolAddress((void**)&ffh,  g_ffh);
    cudaGetSymbolAddress((void**)&x2h,  g_x2h);
    cudaGetSymbolAddress((void**)&wr,   g_wr);

    cudaFuncSetAttribute(gemm_mma<0>, cudaFuncAttributeMaxDynamicSharedMemorySize, SMEM3);
    cudaFuncSetAttribute(gemm_mma<2>, cudaFuncAttributeMaxDynamicSharedMemorySize, SMEM3);
    cudaFuncSetAttribute(gemm_mma<5>, cudaFuncAttributeMaxDynamicSharedMemorySize, SMEM3);
    cudaFuncSetAttribute(gemm_mma<7>, cudaFuncAttributeMaxDynamicSharedMemorySize, SMEM3);
    cudaFuncSetAttribute(gemm_mma<8>, cudaFuncAttributeMaxDynamicSharedMemorySize, SMEM3);
    cudaFuncSetAttribute(gemm_mma<9>, cudaFuncAttributeMaxDynamicSharedMemorySize, SMEM3);

    // --- convert weights to fp16 (qkv packed into [1024][3072]) ---
    const int n4_d  = DIM*DIM/4;
    const int n4_ff = DIM*FFD/4;
    cvt_qkv<<<n4_d/256, 256>>>(wq, wr + OFF_QKV, 0);
    cvt_qkv<<<n4_d/256, 256>>>(wk, wr + OFF_QKV, 1024);
    cvt_qkv<<<n4_d/256, 256>>>(wv, wr + OFF_QKV, 2048);
    cvt_kernel<<<n4_d/256, 256>>>(wo,   wr + OFF_WO,   n4_d);
    cvt_kernel<<<n4_d/256, 256>>>(wd,   wr + OFF_WD,   n4_d);
    cvt_kernel<<<n4_ff/256, 256>>>(wff1, wr + OFF_WFF1, n4_ff);
    cvt_kernel<<<n4_ff/256, 256>>>(wff2, wr + OFF_WFF2, n4_ff);

    // --- attention block ---
    ln_kernel<<<TOK, 256>>>(x, ln1g, ln1b, h);
    gemm_mma<7><<<dim3(24, 128), 256, SMEM3>>>(h, wr + OFF_QKV,
                                               (const float*)kh, (const float*)vh,
                                               qh, 3*DIM, DIM);
    qsm_kernel<<<8192, 256>>>(qh);                 /* 65536 rows, 8 warps/block */
    ksm_partial<<<dim3(KCH, NBH), 256>>>(kh, part);
    ksm_norm   <<<dim3(KCH, NBH), 256>>>(kh, part);
    ctx_mma    <<<dim3(4, 4, NBH), 128>>>(kh, vh, ctxh);
    /* W2_b[head block] = ctx_{b,h} @ wo_h : 16 batched 256x1024x256 GEMMs */
    gemm_mma<8><<<dim3(8, 2, NBH), 256, SMEM3>>>(ctxh, wr + OFF_WO, nullptr, nullptr,
                                                 w2h, DIM, DH);
    /* x1_b = q_b @ W2_b + bo + x_b : batched over BATCH */
    gemm_mma<9><<<dim3(8, 32, BATCH), 256, SMEM3>>>(qh, w2h, bo, x, x1, DIM, DIM);

    // --- FFN block ---
    ln_kernel<<<TOK, 256>>>(x1, ln2g, ln2b, h);
    gemm_mma<2><<<dim3(32, 128), 256, SMEM3>>>(h, wr + OFF_WFF1, bff1, nullptr, ffh, FFD, DIM);
    gemm_mma<5><<<dim3(8, 128), 256, SMEM3>>>(ffh, wr + OFF_WFF2, bff2, x1, x2h, DIM, FFD);

    // --- trailing dense ---
    gemm_mma<0><<<dim3(8, 128), 256, SMEM3>>>(x2h, wr + OFF_WD, bd, nullptr, out, DIM, DIM);
}